// round 7
// baseline (speedup 1.0000x reference)
#include <cuda_runtime.h>
#include <cstdint>
#include <cstddef>

#define D_MODEL 1024
#define HEADS   16
#define D_K     64
#define BATCH   2
#define SEQ     2048
#define M_TOTAL (BATCH * SEQ)   // 4096

// Scratch (allocation-free rule: __device__ globals)
__device__ float g_Q[M_TOTAL * D_MODEL];
__device__ float g_K[M_TOTAL * D_MODEL];
__device__ float g_V[M_TOTAL * D_MODEL];
__device__ float g_ctx[M_TOTAL * D_MODEL];

// ---------------------------------------------------------------------------
// tf32 helpers (baseline PTX, legal on compute_103)
// ---------------------------------------------------------------------------
__device__ __forceinline__ float tf32_rna(float x) {
    uint32_t r;
    asm("cvt.rna.tf32.f32 %0, %1;" : "=r"(r) : "f"(x));
    return __uint_as_float(r);
}
__device__ __forceinline__ uint32_t tf32u(float x) {
    uint32_t r;
    asm("cvt.rna.tf32.f32 %0, %1;" : "=r"(r) : "f"(x));
    return r;
}

__device__ __forceinline__ void mma_tf32_16x8x8(
    float& d0, float& d1, float& d2, float& d3,
    uint32_t a0, uint32_t a1, uint32_t a2, uint32_t a3,
    uint32_t b0, uint32_t b1)
{
    asm volatile(
        "mma.sync.aligned.m16n8k8.row.col.f32.tf32.tf32.f32 "
        "{%0,%1,%2,%3}, {%4,%5,%6,%7}, {%8,%9}, {%0,%1,%2,%3};"
        : "+f"(d0), "+f"(d1), "+f"(d2), "+f"(d3)
        : "r"(a0), "r"(a1), "r"(a2), "r"(a3), "r"(b0), "r"(b1));
}

// pair-permutation of an inner index: (k, k+4) within each 8-group become adjacent
// perm(k) = (k & ~7) + 2*(k & 3) + ((k >> 2) & 1)
__device__ __forceinline__ int perm_idx(int k) {
    return (k & ~7) + ((k & 3) << 1) + ((k >> 2) & 1);
}

// ---------------------------------------------------------------------------
// tf32 mma.sync GEMM body (NT + bias): C[M,N] = A[M,K] * W[N,K]^T + bias[N]
// 128x128 CTA tile, BK=32, 256 threads (8 warps, 2x4), 64x32 warp tile.
// Double-buffered smem, PAIR-PERMUTED k layout -> LDS.64 fragment loads.
// ---------------------------------------------------------------------------
#define BM  128
#define BN  128
#define BKG 32
#define LDP 40                                       // 32 + 8 pad; 40%32==8 -> conflict-free LDS.64
#define TILE_FLOATS (BM * LDP)                       // 5120
#define GEMM_SMEM_BYTES (4 * TILE_FLOATS * 4)        // A0,B0,A1,B1 = 81920 B

__device__ __forceinline__ void stage_store(
    float* __restrict__ As, float* __restrict__ Bs,
    const float4* pa, const float4* pb, int ldr, int ldc4)
{
    // float4 covers k = ldc4*4 .. +3 -> perm positions base+0,2,4,6
    const int kb = ((ldc4 >> 1) << 3) + (ldc4 & 1);
    #pragma unroll
    for (int i = 0; i < 4; i++) {
        int r = ldr + i * 32;
        float4 va = pa[i], vb = pb[i];
        float* a = As + r * LDP + kb;
        a[0] = tf32_rna(va.x); a[2] = tf32_rna(va.y);
        a[4] = tf32_rna(va.z); a[6] = tf32_rna(va.w);
        float* bb = Bs + r * LDP + kb;
        bb[0] = tf32_rna(vb.x); bb[2] = tf32_rna(vb.y);
        bb[4] = tf32_rna(vb.z); bb[6] = tf32_rna(vb.w);
    }
}

__device__ __forceinline__ void gemm_body(
    const float* __restrict__ A,
    const float* __restrict__ W,
    const float* __restrict__ bias,
    float* __restrict__ C,
    int M, int N, int K)
{
    extern __shared__ float smp[];
    float* As0 = smp;
    float* Bs0 = smp + TILE_FLOATS;
    float* As1 = smp + 2 * TILE_FLOATS;
    float* Bs1 = smp + 3 * TILE_FLOATS;

    const int tid  = threadIdx.x;
    const int wid  = tid >> 5;
    const int lane = tid & 31;
    const int wm = wid & 1;
    const int wn = wid >> 1;
    const int rowBase = blockIdx.y * BM;
    const int colBase = blockIdx.x * BN;
    const int warpRow = wm * 64;
    const int warpCol = wn * 32;

    const int ldr  = tid >> 3;
    const int ldc4 = tid & 7;

    float acc[4][4][4];
    #pragma unroll
    for (int mt = 0; mt < 4; mt++)
        #pragma unroll
        for (int nt = 0; nt < 4; nt++)
            #pragma unroll
            for (int i = 0; i < 4; i++) acc[mt][nt][i] = 0.f;

    float4 pa[4], pb[4];

    #pragma unroll
    for (int i = 0; i < 4; i++) {
        int r = ldr + i * 32;
        pa[i] = *reinterpret_cast<const float4*>(&A[(size_t)(rowBase + r) * K + ldc4 * 4]);
        pb[i] = *reinterpret_cast<const float4*>(&W[(size_t)(colBase + r) * K + ldc4 * 4]);
    }
    stage_store(As0, Bs0, pa, pb, ldr, ldc4);
    __syncthreads();

    const int NT = K / BKG;
    for (int t = 0; t < NT; t++) {
        const float* Ac = (t & 1) ? As1 : As0;
        const float* Bc = (t & 1) ? Bs1 : Bs0;
        const bool more = (t + 1 < NT);

        if (more) {
            const int ktn = (t + 1) * BKG;
            #pragma unroll
            for (int i = 0; i < 4; i++) {
                int r = ldr + i * 32;
                pa[i] = *reinterpret_cast<const float4*>(
                    &A[(size_t)(rowBase + r) * K + ktn + ldc4 * 4]);
                pb[i] = *reinterpret_cast<const float4*>(
                    &W[(size_t)(colBase + r) * K + ktn + ldc4 * 4]);
            }
        }

        const int r0 = warpRow + (lane >> 2);
        const int n0 = warpCol + (lane >> 2);
        const int c2 = (lane & 3) << 1;
        #pragma unroll
        for (int kk = 0; kk < BKG; kk += 8) {
            // fragment loads: (k, k+4) adjacent after perm -> LDS.64
            uint32_t af[4][4], bf[4][2];
            #pragma unroll
            for (int mt = 0; mt < 4; mt++) {
                float2 lo = *reinterpret_cast<const float2*>(&Ac[(r0 + mt*16    ) * LDP + kk + c2]);
                float2 hi = *reinterpret_cast<const float2*>(&Ac[(r0 + mt*16 + 8) * LDP + kk + c2]);
                af[mt][0] = __float_as_uint(lo.x);
                af[mt][2] = __float_as_uint(lo.y);
                af[mt][1] = __float_as_uint(hi.x);
                af[mt][3] = __float_as_uint(hi.y);
            }
            #pragma unroll
            for (int nt = 0; nt < 4; nt++) {
                float2 bv = *reinterpret_cast<const float2*>(&Bc[(n0 + nt*8) * LDP + kk + c2]);
                bf[nt][0] = __float_as_uint(bv.x);
                bf[nt][1] = __float_as_uint(bv.y);
            }
            #pragma unroll
            for (int mt = 0; mt < 4; mt++)
                #pragma unroll
                for (int nt = 0; nt < 4; nt++)
                    mma_tf32_16x8x8(acc[mt][nt][0], acc[mt][nt][1],
                                    acc[mt][nt][2], acc[mt][nt][3],
                                    af[mt][0], af[mt][1], af[mt][2], af[mt][3],
                                    bf[nt][0], bf[nt][1]);
        }

        if (more) {
            float* An = (t & 1) ? As0 : As1;
            float* Bn = (t & 1) ? Bs0 : Bs1;
            stage_store(An, Bn, pa, pb, ldr, ldc4);
            __syncthreads();
        }
    }

    #pragma unroll
    for (int nt = 0; nt < 4; nt++) {
        const int col = colBase + warpCol + nt * 8 + 2 * (lane & 3);
        const float b0 = bias[col], b1 = bias[col + 1];
        #pragma unroll
        for (int mt = 0; mt < 4; mt++) {
            const int row = rowBase + warpRow + mt * 16 + (lane >> 2);
            float2 v0 = make_float2(acc[mt][nt][0] + b0, acc[mt][nt][1] + b1);
            float2 v1 = make_float2(acc[mt][nt][2] + b0, acc[mt][nt][3] + b1);
            *reinterpret_cast<float2*>(&C[(size_t)row * N + col])       = v0;
            *reinterpret_cast<float2*>(&C[(size_t)(row + 8) * N + col]) = v1;
        }
    }
}

// Single GEMM (output projection)
__global__ __launch_bounds__(256, 2)
void gemm_tf32_mma(const float* __restrict__ A,
                   const float* __restrict__ W,
                   const float* __restrict__ bias,
                   float* __restrict__ C,
                   int M, int N, int K)
{
    gemm_body(A, W, bias, C, M, N, K);
}

// Fused Q/K/V projections: blockIdx.z selects the operand triplet.
__global__ __launch_bounds__(256, 2)
void gemm_tf32_qkv(const float* __restrict__ qin,  const float* __restrict__ kin,
                   const float* __restrict__ vin,
                   const float* __restrict__ wq,   const float* __restrict__ wk,
                   const float* __restrict__ wv,
                   const float* __restrict__ bq,   const float* __restrict__ bk,
                   const float* __restrict__ bv,
                   float* __restrict__ Qo, float* __restrict__ Ko, float* __restrict__ Vo)
{
    const float *A, *W, *bias;
    float* C;
    if (blockIdx.z == 0)      { A = qin; W = wq; bias = bq; C = Qo; }
    else if (blockIdx.z == 1) { A = kin; W = wk; bias = bk; C = Ko; }
    else                      { A = vin; W = wv; bias = bv; C = Vo; }
    gemm_body(A, W, bias, C, M_TOTAL, D_MODEL, D_MODEL);
}

// ---------------------------------------------------------------------------
// Tensor-core causal flash attention (tf32 mma.sync), software-pipelined K/V,
// pair-permuted smem layouts -> LDS.64 fragment loads in the hot loop.
// CTA: 128 q-rows, 256 threads (8 warps x m16 row band). Heaviest-first order.
// ---------------------------------------------------------------------------
#define AQ  128
#define AKV 64
#define AP  72   // 64 + 8 pad; 72%32==8 -> conflict-free LDS.64 frag reads

__global__ __launch_bounds__(256, 1)
void flash_attn_tc(const float* __restrict__ Qg,
                   const float* __restrict__ Kg,
                   const float* __restrict__ Vg,
                   float* __restrict__ Og)
{
    __shared__ float sA[64 * AP];   // Q rows 0-63 staging, then K tile [key][perm(d)]
    __shared__ float sB[64 * AP];   // Q rows 64-127 staging, then V^T tile [d][perm(key)]

    const int tid  = threadIdx.x;
    const int w    = tid >> 5;
    const int lane = tid & 31;
    const int h = blockIdx.y, b = blockIdx.z;
    const int qblk = (int)gridDim.x - 1 - (int)blockIdx.x;
    const int qbase = qblk * AQ;

    const float* Qb = Qg + (size_t)b * SEQ * D_MODEL + h * D_K;
    const float* Kb = Kg + (size_t)b * SEQ * D_MODEL + h * D_K;
    const float* Vb = Vg + (size_t)b * SEQ * D_MODEL + h * D_K;
    float*       Ob = Og + (size_t)b * SEQ * D_MODEL + h * D_K;

    // ---- stage Q (scaled by 1/sqrt(64), tf32-rounded, perm over d) ----
    #pragma unroll
    for (int i = 0; i < 8; i++) {
        int idx = tid + i * 256;
        int r = idx >> 4, d4 = idx & 15;
        float4 v = *reinterpret_cast<const float4*>(
            &Qb[(size_t)(qbase + r) * D_MODEL + d4 * 4]);
        const int kb = ((d4 >> 1) << 3) + (d4 & 1);
        float* dst = (r < 64 ? sA : sB) + (r & 63) * AP + kb;
        dst[0] = tf32_rna(v.x * 0.125f);
        dst[2] = tf32_rna(v.y * 0.125f);
        dst[4] = tf32_rna(v.z * 0.125f);
        dst[6] = tf32_rna(v.w * 0.125f);
    }
    __syncthreads();

    // ---- extract Q A-fragments (LDS.64 pairs) ----
    uint32_t qf[8][4];
    {
        const float* qsrc = (w < 4) ? sA : sB;
        int r0 = (w * 16 + (lane >> 2)) & 63;
        int c2 = (lane & 3) << 1;
        #pragma unroll
        for (int kk = 0; kk < 8; kk++) {
            float2 lo = *reinterpret_cast<const float2*>(&qsrc[ r0      * AP + kk * 8 + c2]);
            float2 hi = *reinterpret_cast<const float2*>(&qsrc[(r0 + 8) * AP + kk * 8 + c2]);
            qf[kk][0] = __float_as_uint(lo.x);
            qf[kk][2] = __float_as_uint(lo.y);
            qf[kk][1] = __float_as_uint(hi.x);
            qf[kk][3] = __float_as_uint(hi.y);
        }
    }
    __syncthreads();

    float of[8][4];
    #pragma unroll
    for (int j = 0; j < 8; j++) { of[j][0]=of[j][1]=of[j][2]=of[j][3]=0.f; }
    float m0 = -1e30f, m1 = -1e30f, l0 = 0.f, l1 = 0.f;

    const int rowg0 = qbase + w * 16 + (lane >> 2);
    const int rowg1 = rowg0 + 8;
    const int warpRowMax = qbase + w * 16 + 15;
    const int nchunks = (qbase + AQ) / AKV;

    const int cbase = lane & ~3, cq = lane & 3;
    const int cq2 = cq << 1;
    const int slo = cbase | (cq >> 1);
    const int shi = slo + 2;
    const bool odd = cq & 1;

    // ---- fill chunk 0 (K perm over d; V^T perm over key) ----
    #pragma unroll
    for (int i = 0; i < 4; i++) {
        int idx = tid + i * 256;
        int r = idx >> 4, d4 = idx & 15;
        float4 kv = *reinterpret_cast<const float4*>(&Kb[(size_t)r * D_MODEL + d4 * 4]);
        const int kb = ((d4 >> 1) << 3) + (d4 & 1);
        float* dk = sA + r * AP + kb;
        dk[0]=tf32_rna(kv.x); dk[2]=tf32_rna(kv.y);
        dk[4]=tf32_rna(kv.z); dk[6]=tf32_rna(kv.w);
        float4 vv = *reinterpret_cast<const float4*>(&Vb[(size_t)r * D_MODEL + d4 * 4]);
        const int pr = perm_idx(r);
        sB[(d4*4+0)*AP + pr] = tf32_rna(vv.x);
        sB[(d4*4+1)*AP + pr] = tf32_rna(vv.y);
        sB[(d4*4+2)*AP + pr] = tf32_rna(vv.z);
        sB[(d4*4+3)*AP + pr] = tf32_rna(vv.w);
    }
    __syncthreads();

    for (int ch = 0; ch < nchunks; ch++) {
        const int kt = ch * AKV;
        const bool hasNext = (ch + 1 < nchunks);

        float4 pk[4], pv[4];
        if (hasNext) {
            const int ktn = kt + AKV;
            #pragma unroll
            for (int i = 0; i < 4; i++) {
                int idx = tid + i * 256;
                int r = idx >> 4, d4 = idx & 15;
                pk[i] = *reinterpret_cast<const float4*>(
                    &Kb[(size_t)(ktn + r) * D_MODEL + d4 * 4]);
                pv[i] = *reinterpret_cast<const float4*>(
                    &Vb[(size_t)(ktn + r) * D_MODEL + d4 * 4]);
            }
        }

        if (kt <= warpRowMax) {
            // ---- S = Q K^T (B-frags via LDS.64) ----
            float cf[8][4];
            #pragma unroll
            for (int j = 0; j < 8; j++) {
                cf[j][0]=cf[j][1]=cf[j][2]=cf[j][3]=0.f;
                const int key = j * 8 + (lane >> 2);
                #pragma unroll
                for (int kk = 0; kk < 8; kk++) {
                    float2 bv = *reinterpret_cast<const float2*>(&sA[key*AP + kk*8 + cq2]);
                    mma_tf32_16x8x8(cf[j][0], cf[j][1], cf[j][2], cf[j][3],
                                    qf[kk][0], qf[kk][1], qf[kk][2], qf[kk][3],
                                    __float_as_uint(bv.x), __float_as_uint(bv.y));
                }
            }

            if (kt + AKV - 1 > qbase + w * 16) {
                #pragma unroll
                for (int j = 0; j < 8; j++) {
                    int col = kt + j * 8 + 2 * cq;
                    if (col     > rowg0) cf[j][0] = -1e30f;
                    if (col + 1 > rowg0) cf[j][1] = -1e30f;
                    if (col     > rowg1) cf[j][2] = -1e30f;
                    if (col + 1 > rowg1) cf[j][3] = -1e30f;
                }
            }

            float mx0 = -1e30f, mx1 = -1e30f;
            #pragma unroll
            for (int j = 0; j < 8; j++) {
                mx0 = fmaxf(mx0, fmaxf(cf[j][0], cf[j][1]));
                mx1 = fmaxf(mx1, fmaxf(cf[j][2], cf[j][3]));
            }
            mx0 = fmaxf(mx0, __shfl_xor_sync(0xFFFFFFFFu, mx0, 1));
            mx0 = fmaxf(mx0, __shfl_xor_sync(0xFFFFFFFFu, mx0, 2));
            mx1 = fmaxf(mx1, __shfl_xor_sync(0xFFFFFFFFu, mx1, 1));
            mx1 = fmaxf(mx1, __shfl_xor_sync(0xFFFFFFFFu, mx1, 2));

            const float mn0 = fmaxf(m0, mx0), mn1 = fmaxf(m1, mx1);
            const float corr0 = __expf(m0 - mn0), corr1 = __expf(m1 - mn1);
            m0 = mn0; m1 = mn1;

            float la0 = 0.f, la1 = 0.f;
            #pragma unroll
            for (int j = 0; j < 8; j++) {
                cf[j][0] = __expf(cf[j][0] - mn0);
                cf[j][1] = __expf(cf[j][1] - mn0);
                cf[j][2] = __expf(cf[j][2] - mn1);
                cf[j][3] = __expf(cf[j][3] - mn1);
                la0 += cf[j][0] + cf[j][1];
                la1 += cf[j][2] + cf[j][3];
            }
            la0 += __shfl_xor_sync(0xFFFFFFFFu, la0, 1);
            la0 += __shfl_xor_sync(0xFFFFFFFFu, la0, 2);
            la1 += __shfl_xor_sync(0xFFFFFFFFu, la1, 1);
            la1 += __shfl_xor_sync(0xFFFFFFFFu, la1, 2);
            l0 = l0 * corr0 + la0;
            l1 = l1 * corr1 + la1;

            #pragma unroll
            for (int j = 0; j < 8; j++) {
                of[j][0] *= corr0; of[j][1] *= corr0;
                of[j][2] *= corr1; of[j][3] *= corr1;
            }

            // ---- O += P V (C-frag -> A-frag shuffles; B-frags via LDS.64) ----
            #pragma unroll
            for (int kk = 0; kk < 8; kk++) {
                uint32_t p0 = tf32u(cf[kk][0]), p1 = tf32u(cf[kk][1]);
                uint32_t p2 = tf32u(cf[kk][2]), p3 = tf32u(cf[kk][3]);
                uint32_t u0 = __shfl_sync(0xFFFFFFFFu, p0, slo);
                uint32_t u1 = __shfl_sync(0xFFFFFFFFu, p1, slo);
                uint32_t u2 = __shfl_sync(0xFFFFFFFFu, p2, slo);
                uint32_t u3 = __shfl_sync(0xFFFFFFFFu, p3, slo);
                uint32_t x0 = __shfl_sync(0xFFFFFFFFu, p0, shi);
                uint32_t x1 = __shfl_sync(0xFFFFFFFFu, p1, shi);
                uint32_t x2 = __shfl_sync(0xFFFFFFFFu, p2, shi);
                uint32_t x3 = __shfl_sync(0xFFFFFFFFu, p3, shi);
                uint32_t a0 = odd ? u1 : u0;
                uint32_t a1 = odd ? u3 : u2;
                uint32_t a2 = odd ? x1 : x0;
                uint32_t a3 = odd ? x3 : x2;
                #pragma unroll
                for (int j2 = 0; j2 < 8; j2++) {
                    const int d = j2 * 8 + (lane >> 2);
                    float2 bv = *reinterpret_cast<const float2*>(&sB[d*AP + kk*8 + cq2]);
                    mma_tf32_16x8x8(of[j2][0], of[j2][1], of[j2][2], of[j2][3],
                                    a0, a1, a2, a3,
                                    __float_as_uint(bv.x), __float_as_uint(bv.y));
                }
            }
        }
        __syncthreads();

        if (hasNext) {
            #pragma unroll
            for (int i = 0; i < 4; i++) {
                int idx = tid + i * 256;
                int r = idx >> 4, d4 = idx & 15;
                const int kb = ((d4 >> 1) << 3) + (d4 & 1);
                float* dk = sA + r * AP + kb;
                dk[0]=tf32_rna(pk[i].x); dk[2]=tf32_rna(pk[i].y);
                dk[4]=tf32_rna(pk[i].z); dk[6]=tf32_rna(pk[i].w);
                const int pr = perm_idx(r);
                sB[(d4*4+0)*AP + pr] = tf32_rna(pv[i].x);
                sB[(d4*4+1)*AP + pr] = tf32_rna(pv[i].y);
                sB[(d4*4+2)*AP + pr] = tf32_rna(pv[i].z);
                sB[(d4*4+3)*AP + pr] = tf32_rna(pv[i].w);
            }
            __syncthreads();
        }
    }

    const float inv0 = 1.f / l0, inv1 = 1.f / l1;
    #pragma unroll
    for (int j2 = 0; j2 < 8; j2++) {
        int col = j2 * 8 + 2 * cq;
        float2 v0 = make_float2(of[j2][0] * inv0, of[j2][1] * inv0);
        float2 v1 = make_float2(of[j2][2] * inv1, of[j2][3] * inv1);
        *reinterpret_cast<float2*>(&Ob[(size_t)rowg0 * D_MODEL + col]) = v0;
        *reinterpret_cast<float2*>(&Ob[(size_t)rowg1 * D_MODEL + col]) = v1;
    }
}

// ---------------------------------------------------------------------------
// Launch
// ---------------------------------------------------------------------------
extern "C" void kernel_launch(void* const* d_in, const int* in_sizes, int n_in,
                              void* d_out, int out_size)
{
    (void)in_sizes; (void)n_in; (void)out_size;
    const float* q    = (const float*)d_in[0];
    const float* k    = (const float*)d_in[1];
    const float* v    = (const float*)d_in[2];
    // d_in[3] = mask (causal tril) — analytic
    const float* wq_w = (const float*)d_in[4];
    const float* wq_b = (const float*)d_in[5];
    const float* wk_w = (const float*)d_in[6];
    const float* wk_b = (const float*)d_in[7];
    const float* wv_w = (const float*)d_in[8];
    const float* wv_b = (const float*)d_in[9];
    const float* wo_w = (const float*)d_in[10];
    const float* wo_b = (const float*)d_in[11];
    float* out = (float*)d_out;

    void *pQ, *pK, *pV, *pC;
    cudaGetSymbolAddress(&pQ, g_Q);
    cudaGetSymbolAddress(&pK, g_K);
    cudaGetSymbolAddress(&pV, g_V);
    cudaGetSymbolAddress(&pC, g_ctx);
    float* Qp = (float*)pQ;
    float* Kp = (float*)pK;
    float* Vp = (float*)pV;
    float* Cp = (float*)pC;

    cudaFuncSetAttribute(gemm_tf32_qkv,
                         cudaFuncAttributeMaxDynamicSharedMemorySize, GEMM_SMEM_BYTES);
    cudaFuncSetAttribute(gemm_tf32_mma,
                         cudaFuncAttributeMaxDynamicSharedMemorySize, GEMM_SMEM_BYTES);

    dim3 qkvGrid(D_MODEL / BN, M_TOTAL / BM, 3);   // (8, 32, 3) = 768 CTAs
    gemm_tf32_qkv<<<qkvGrid, 256, GEMM_SMEM_BYTES>>>(q, k, v, wq_w, wk_w, wv_w,
                                                     wq_b, wk_b, wv_b, Qp, Kp, Vp);

    dim3 attnGrid(SEQ / AQ, HEADS, BATCH);         // (16, 16, 2)
    flash_attn_tc<<<attnGrid, 256>>>(Qp, Kp, Vp, Cp);

    dim3 gemmGrid(D_MODEL / BN, M_TOTAL / BM);     // (8, 32)
    gemm_tf32_mma<<<gemmGrid, 256, GEMM_SMEM_BYTES>>>(Cp, wo_w, wo_b, out,
                                                      M_TOTAL, D_MODEL, D_MODEL);
}

// round 8
// speedup vs baseline: 1.1893x; 1.1893x over previous
#include <cuda_runtime.h>
#include <cstdint>
#include <cstddef>

#define D_MODEL 1024
#define HEADS   16
#define D_K     64
#define BATCH   2
#define SEQ     2048
#define M_TOTAL (BATCH * SEQ)   // 4096

// Scratch (allocation-free rule: __device__ globals)
__device__ float g_Q[M_TOTAL * D_MODEL];
__device__ float g_K[M_TOTAL * D_MODEL];
__device__ float g_V[M_TOTAL * D_MODEL];
__device__ float g_ctx[M_TOTAL * D_MODEL];

// ---------------------------------------------------------------------------
// tf32 helpers (baseline PTX, legal on compute_103)
// ---------------------------------------------------------------------------
__device__ __forceinline__ float tf32_rna(float x) {
    uint32_t r;
    asm("cvt.rna.tf32.f32 %0, %1;" : "=r"(r) : "f"(x));
    return __uint_as_float(r);
}
__device__ __forceinline__ uint32_t tf32u(float x) {
    uint32_t r;
    asm("cvt.rna.tf32.f32 %0, %1;" : "=r"(r) : "f"(x));
    return r;
}

__device__ __forceinline__ void mma_tf32_16x8x8(
    float& d0, float& d1, float& d2, float& d3,
    uint32_t a0, uint32_t a1, uint32_t a2, uint32_t a3,
    uint32_t b0, uint32_t b1)
{
    asm volatile(
        "mma.sync.aligned.m16n8k8.row.col.f32.tf32.tf32.f32 "
        "{%0,%1,%2,%3}, {%4,%5,%6,%7}, {%8,%9}, {%0,%1,%2,%3};"
        : "+f"(d0), "+f"(d1), "+f"(d2), "+f"(d3)
        : "r"(a0), "r"(a1), "r"(a2), "r"(a3), "r"(b0), "r"(b1));
}

// pair-permutation of an inner index within each 8-group:
// perm(k) = (k & ~7) + 2*(k & 3) + ((k >> 2) & 1)   -> (k, k+4) become adjacent
__device__ __forceinline__ int perm_idx(int k) {
    return (k & ~7) + ((k & 3) << 1) + ((k >> 2) & 1);
}

// interleave two float2 (values k,k+1 and k+4,k+5) into the permuted float4
__device__ __forceinline__ float4 perm_pack(float2 lo, float2 hi) {
    float4 v;
    v.x = tf32_rna(lo.x); v.y = tf32_rna(hi.x);
    v.z = tf32_rna(lo.y); v.w = tf32_rna(hi.y);
    return v;
}
__device__ __forceinline__ float4 perm_pack_scaled(float2 lo, float2 hi, float s) {
    float4 v;
    v.x = tf32_rna(lo.x * s); v.y = tf32_rna(hi.x * s);
    v.z = tf32_rna(lo.y * s); v.w = tf32_rna(hi.y * s);
    return v;
}

// ---------------------------------------------------------------------------
// tf32 mma.sync GEMM body (NT + bias): C[M,N] = A[M,K] * W[N,K]^T + bias[N]
// 128x128 CTA tile, BK=32, 256 threads (8 warps, 2x4), 64x32 warp tile.
// Double-buffered smem; permutation applied in the global->register path so
// staging stays STS.128 while fragment reads are LDS.64.
// ---------------------------------------------------------------------------
#define BM  128
#define BN  128
#define BKG 32
#define LDP 40                                       // 40 % 32 == 8 -> conflict-free LDS.64
#define TILE_FLOATS (BM * LDP)                       // 5120
#define GEMM_SMEM_BYTES (4 * TILE_FLOATS * 4)        // A0,B0,A1,B1 = 81920 B

__device__ __forceinline__ void gemm_body(
    const float* __restrict__ A,
    const float* __restrict__ W,
    const float* __restrict__ bias,
    float* __restrict__ C,
    int M, int N, int K)
{
    extern __shared__ float smp[];
    float* As0 = smp;
    float* Bs0 = smp + TILE_FLOATS;
    float* As1 = smp + 2 * TILE_FLOATS;
    float* Bs1 = smp + 3 * TILE_FLOATS;

    const int tid  = threadIdx.x;
    const int wid  = tid >> 5;
    const int lane = tid & 31;
    const int wm = wid & 1;
    const int wn = wid >> 1;
    const int rowBase = blockIdx.y * BM;
    const int colBase = blockIdx.x * BN;
    const int warpRow = wm * 64;
    const int warpCol = wn * 32;

    const int ldr  = tid >> 3;        // 0..31 (+32/64/96)
    const int ldc4 = tid & 7;         // which permuted float4 within the 32-k row
    // global source base for this permuted float4: pair (kg, kg+4)
    const int kg = ((ldc4 >> 1) << 3) + ((ldc4 & 1) << 1);

    float acc[4][4][4];
    #pragma unroll
    for (int mt = 0; mt < 4; mt++)
        #pragma unroll
        for (int nt = 0; nt < 4; nt++)
            #pragma unroll
            for (int i = 0; i < 4; i++) acc[mt][nt][i] = 0.f;

    float2 paL[4], paH[4], pbL[4], pbH[4];

    #pragma unroll
    for (int i = 0; i < 4; i++) {
        int r = ldr + i * 32;
        const float* a = &A[(size_t)(rowBase + r) * K + kg];
        const float* b = &W[(size_t)(colBase + r) * K + kg];
        paL[i] = *reinterpret_cast<const float2*>(a);
        paH[i] = *reinterpret_cast<const float2*>(a + 4);
        pbL[i] = *reinterpret_cast<const float2*>(b);
        pbH[i] = *reinterpret_cast<const float2*>(b + 4);
    }
    #pragma unroll
    for (int i = 0; i < 4; i++) {
        int r = ldr + i * 32;
        *reinterpret_cast<float4*>(As0 + r * LDP + ldc4 * 4) = perm_pack(paL[i], paH[i]);
        *reinterpret_cast<float4*>(Bs0 + r * LDP + ldc4 * 4) = perm_pack(pbL[i], pbH[i]);
    }
    __syncthreads();

    const int NT = K / BKG;
    for (int t = 0; t < NT; t++) {
        const float* Ac = (t & 1) ? As1 : As0;
        const float* Bc = (t & 1) ? Bs1 : Bs0;
        const bool more = (t + 1 < NT);

        if (more) {
            const int ktn = (t + 1) * BKG;
            #pragma unroll
            for (int i = 0; i < 4; i++) {
                int r = ldr + i * 32;
                const float* a = &A[(size_t)(rowBase + r) * K + ktn + kg];
                const float* b = &W[(size_t)(colBase + r) * K + ktn + kg];
                paL[i] = *reinterpret_cast<const float2*>(a);
                paH[i] = *reinterpret_cast<const float2*>(a + 4);
                pbL[i] = *reinterpret_cast<const float2*>(b);
                pbH[i] = *reinterpret_cast<const float2*>(b + 4);
            }
        }

        const int r0 = warpRow + (lane >> 2);
        const int n0 = warpCol + (lane >> 2);
        const int c2 = (lane & 3) << 1;
        #pragma unroll
        for (int kk = 0; kk < BKG; kk += 8) {
            uint32_t af[4][4], bf[4][2];
            #pragma unroll
            for (int mt = 0; mt < 4; mt++) {
                float2 lo = *reinterpret_cast<const float2*>(&Ac[(r0 + mt*16    ) * LDP + kk + c2]);
                float2 hi = *reinterpret_cast<const float2*>(&Ac[(r0 + mt*16 + 8) * LDP + kk + c2]);
                af[mt][0] = __float_as_uint(lo.x);
                af[mt][2] = __float_as_uint(lo.y);
                af[mt][1] = __float_as_uint(hi.x);
                af[mt][3] = __float_as_uint(hi.y);
            }
            #pragma unroll
            for (int nt = 0; nt < 4; nt++) {
                float2 bv = *reinterpret_cast<const float2*>(&Bc[(n0 + nt*8) * LDP + kk + c2]);
                bf[nt][0] = __float_as_uint(bv.x);
                bf[nt][1] = __float_as_uint(bv.y);
            }
            #pragma unroll
            for (int mt = 0; mt < 4; mt++)
                #pragma unroll
                for (int nt = 0; nt < 4; nt++)
                    mma_tf32_16x8x8(acc[mt][nt][0], acc[mt][nt][1],
                                    acc[mt][nt][2], acc[mt][nt][3],
                                    af[mt][0], af[mt][1], af[mt][2], af[mt][3],
                                    bf[nt][0], bf[nt][1]);
        }

        if (more) {
            float* An = (t & 1) ? As0 : As1;
            float* Bn = (t & 1) ? Bs0 : Bs1;
            #pragma unroll
            for (int i = 0; i < 4; i++) {
                int r = ldr + i * 32;
                *reinterpret_cast<float4*>(An + r * LDP + ldc4 * 4) = perm_pack(paL[i], paH[i]);
                *reinterpret_cast<float4*>(Bn + r * LDP + ldc4 * 4) = perm_pack(pbL[i], pbH[i]);
            }
            __syncthreads();
        }
    }

    #pragma unroll
    for (int nt = 0; nt < 4; nt++) {
        const int col = colBase + warpCol + nt * 8 + 2 * (lane & 3);
        const float b0 = bias[col], b1 = bias[col + 1];
        #pragma unroll
        for (int mt = 0; mt < 4; mt++) {
            const int row = rowBase + warpRow + mt * 16 + (lane >> 2);
            float2 v0 = make_float2(acc[mt][nt][0] + b0, acc[mt][nt][1] + b1);
            float2 v1 = make_float2(acc[mt][nt][2] + b0, acc[mt][nt][3] + b1);
            *reinterpret_cast<float2*>(&C[(size_t)row * N + col])       = v0;
            *reinterpret_cast<float2*>(&C[(size_t)(row + 8) * N + col]) = v1;
        }
    }
}

// Single GEMM (output projection)
__global__ __launch_bounds__(256, 2)
void gemm_tf32_mma(const float* __restrict__ A,
                   const float* __restrict__ W,
                   const float* __restrict__ bias,
                   float* __restrict__ C,
                   int M, int N, int K)
{
    gemm_body(A, W, bias, C, M, N, K);
}

// Fused Q/K/V projections: blockIdx.z selects the operand triplet.
__global__ __launch_bounds__(256, 2)
void gemm_tf32_qkv(const float* __restrict__ qin,  const float* __restrict__ kin,
                   const float* __restrict__ vin,
                   const float* __restrict__ wq,   const float* __restrict__ wk,
                   const float* __restrict__ wv,
                   const float* __restrict__ bq,   const float* __restrict__ bk,
                   const float* __restrict__ bv,
                   float* __restrict__ Qo, float* __restrict__ Ko, float* __restrict__ Vo)
{
    const float *A, *W, *bias;
    float* C;
    if (blockIdx.z == 0)      { A = qin; W = wq; bias = bq; C = Qo; }
    else if (blockIdx.z == 1) { A = kin; W = wk; bias = bk; C = Ko; }
    else                      { A = vin; W = wv; bias = bv; C = Vo; }
    gemm_body(A, W, bias, C, M_TOTAL, D_MODEL, D_MODEL);
}

// ---------------------------------------------------------------------------
// Tensor-core causal flash attention (tf32 mma.sync), software-pipelined K/V.
// Permuted layouts with STS.128 staging for Q/K, conflict-free V^T staging.
// CTA: 128 q-rows, 256 threads (8 warps x m16 row band). Heaviest-first order.
// ---------------------------------------------------------------------------
#define AQ  128
#define AKV 64
#define AP  72   // 72 % 32 == 8 -> conflict-free LDS.64 frag reads

__global__ __launch_bounds__(256, 1)
void flash_attn_tc(const float* __restrict__ Qg,
                   const float* __restrict__ Kg,
                   const float* __restrict__ Vg,
                   float* __restrict__ Og)
{
    __shared__ float sA[64 * AP];   // Q rows 0-63 staging, then K tile [key][perm(d)]
    __shared__ float sB[64 * AP];   // Q rows 64-127 staging, then V^T tile [d][perm(key)]

    const int tid  = threadIdx.x;
    const int w    = tid >> 5;
    const int lane = tid & 31;
    const int h = blockIdx.y, b = blockIdx.z;
    const int qblk = (int)gridDim.x - 1 - (int)blockIdx.x;
    const int qbase = qblk * AQ;

    const float* Qb = Qg + (size_t)b * SEQ * D_MODEL + h * D_K;
    const float* Kb = Kg + (size_t)b * SEQ * D_MODEL + h * D_K;
    const float* Vb = Vg + (size_t)b * SEQ * D_MODEL + h * D_K;
    float*       Ob = Og + (size_t)b * SEQ * D_MODEL + h * D_K;

    // ---- stage Q (scaled, tf32, permuted-in-registers, STS.128) ----
    #pragma unroll
    for (int i = 0; i < 8; i++) {
        int idx = tid + i * 256;
        int r = idx >> 4, d4 = idx & 15;
        const int kg = ((d4 >> 1) << 3) + ((d4 & 1) << 1);
        const float* src = &Qb[(size_t)(qbase + r) * D_MODEL + kg];
        float2 lo = *reinterpret_cast<const float2*>(src);
        float2 hi = *reinterpret_cast<const float2*>(src + 4);
        float* dst = (r < 64 ? sA : sB) + (r & 63) * AP + d4 * 4;
        *reinterpret_cast<float4*>(dst) = perm_pack_scaled(lo, hi, 0.125f);
    }
    __syncthreads();

    // ---- extract Q A-fragments (LDS.64 pairs) ----
    uint32_t qf[8][4];
    {
        const float* qsrc = (w < 4) ? sA : sB;
        int r0 = (w * 16 + (lane >> 2)) & 63;
        int c2 = (lane & 3) << 1;
        #pragma unroll
        for (int kk = 0; kk < 8; kk++) {
            float2 lo = *reinterpret_cast<const float2*>(&qsrc[ r0      * AP + kk * 8 + c2]);
            float2 hi = *reinterpret_cast<const float2*>(&qsrc[(r0 + 8) * AP + kk * 8 + c2]);
            qf[kk][0] = __float_as_uint(lo.x);
            qf[kk][2] = __float_as_uint(lo.y);
            qf[kk][1] = __float_as_uint(hi.x);
            qf[kk][3] = __float_as_uint(hi.y);
        }
    }
    __syncthreads();

    float of[8][4];
    #pragma unroll
    for (int j = 0; j < 8; j++) { of[j][0]=of[j][1]=of[j][2]=of[j][3]=0.f; }
    float m0 = -1e30f, m1 = -1e30f, l0 = 0.f, l1 = 0.f;

    const int rowg0 = qbase + w * 16 + (lane >> 2);
    const int rowg1 = rowg0 + 8;
    const int warpRowMax = qbase + w * 16 + 15;
    const int nchunks = (qbase + AQ) / AKV;

    const int cbase = lane & ~3, cq = lane & 3;
    const int cq2 = cq << 1;
    const int slo = cbase | (cq >> 1);
    const int shi = slo + 2;
    const bool odd = cq & 1;

    // staging index precompute
    const int kr  = tid >> 4;                         // K: key row 0..15 (+16 steps)
    const int kd4 = tid & 15;                         // K: which permuted float4
    const int kkg = ((kd4 >> 1) << 3) + ((kd4 & 1) << 1);
    const int vr  = tid & 63;                         // V: key 0..63
    const int vpr = perm_idx(vr);                     // permuted key position
    const int vd4base = tid >> 6;                     // V: d-group 0..3 (+4 steps)

    // ---- fill chunk 0 ----
    #pragma unroll
    for (int i = 0; i < 4; i++) {
        int r = kr + i * 16;
        const float* src = &Kb[(size_t)r * D_MODEL + kkg];
        float2 lo = *reinterpret_cast<const float2*>(src);
        float2 hi = *reinterpret_cast<const float2*>(src + 4);
        *reinterpret_cast<float4*>(sA + r * AP + kd4 * 4) = perm_pack(lo, hi);

        int d4 = vd4base + i * 4;
        float4 vv = *reinterpret_cast<const float4*>(&Vb[(size_t)vr * D_MODEL + d4 * 4]);
        sB[(d4*4+0)*AP + vpr] = tf32_rna(vv.x);
        sB[(d4*4+1)*AP + vpr] = tf32_rna(vv.y);
        sB[(d4*4+2)*AP + vpr] = tf32_rna(vv.z);
        sB[(d4*4+3)*AP + vpr] = tf32_rna(vv.w);
    }
    __syncthreads();

    for (int ch = 0; ch < nchunks; ch++) {
        const int kt = ch * AKV;
        const bool hasNext = (ch + 1 < nchunks);

        float2 pkL[4], pkH[4];
        float4 pv[4];
        if (hasNext) {
            const int ktn = kt + AKV;
            #pragma unroll
            for (int i = 0; i < 4; i++) {
                int r = kr + i * 16;
                const float* src = &Kb[(size_t)(ktn + r) * D_MODEL + kkg];
                pkL[i] = *reinterpret_cast<const float2*>(src);
                pkH[i] = *reinterpret_cast<const float2*>(src + 4);
                int d4 = vd4base + i * 4;
                pv[i] = *reinterpret_cast<const float4*>(
                    &Vb[(size_t)(ktn + vr) * D_MODEL + d4 * 4]);
            }
        }

        if (kt <= warpRowMax) {
            // ---- S = Q K^T (B-frags via LDS.64) ----
            float cf[8][4];
            #pragma unroll
            for (int j = 0; j < 8; j++) {
                cf[j][0]=cf[j][1]=cf[j][2]=cf[j][3]=0.f;
                const int key = j * 8 + (lane >> 2);
                #pragma unroll
                for (int kk = 0; kk < 8; kk++) {
                    float2 bv = *reinterpret_cast<const float2*>(&sA[key*AP + kk*8 + cq2]);
                    mma_tf32_16x8x8(cf[j][0], cf[j][1], cf[j][2], cf[j][3],
                                    qf[kk][0], qf[kk][1], qf[kk][2], qf[kk][3],
                                    __float_as_uint(bv.x), __float_as_uint(bv.y));
                }
            }

            if (kt + AKV - 1 > qbase + w * 16) {
                #pragma unroll
                for (int j = 0; j < 8; j++) {
                    int col = kt + j * 8 + 2 * cq;
                    if (col     > rowg0) cf[j][0] = -1e30f;
                    if (col + 1 > rowg0) cf[j][1] = -1e30f;
                    if (col     > rowg1) cf[j][2] = -1e30f;
                    if (col + 1 > rowg1) cf[j][3] = -1e30f;
                }
            }

            float mx0 = -1e30f, mx1 = -1e30f;
            #pragma unroll
            for (int j = 0; j < 8; j++) {
                mx0 = fmaxf(mx0, fmaxf(cf[j][0], cf[j][1]));
                mx1 = fmaxf(mx1, fmaxf(cf[j][2], cf[j][3]));
            }
            mx0 = fmaxf(mx0, __shfl_xor_sync(0xFFFFFFFFu, mx0, 1));
            mx0 = fmaxf(mx0, __shfl_xor_sync(0xFFFFFFFFu, mx0, 2));
            mx1 = fmaxf(mx1, __shfl_xor_sync(0xFFFFFFFFu, mx1, 1));
            mx1 = fmaxf(mx1, __shfl_xor_sync(0xFFFFFFFFu, mx1, 2));

            const float mn0 = fmaxf(m0, mx0), mn1 = fmaxf(m1, mx1);
            const float corr0 = __expf(m0 - mn0), corr1 = __expf(m1 - mn1);
            m0 = mn0; m1 = mn1;

            float la0 = 0.f, la1 = 0.f;
            #pragma unroll
            for (int j = 0; j < 8; j++) {
                cf[j][0] = __expf(cf[j][0] - mn0);
                cf[j][1] = __expf(cf[j][1] - mn0);
                cf[j][2] = __expf(cf[j][2] - mn1);
                cf[j][3] = __expf(cf[j][3] - mn1);
                la0 += cf[j][0] + cf[j][1];
                la1 += cf[j][2] + cf[j][3];
            }
            la0 += __shfl_xor_sync(0xFFFFFFFFu, la0, 1);
            la0 += __shfl_xor_sync(0xFFFFFFFFu, la0, 2);
            la1 += __shfl_xor_sync(0xFFFFFFFFu, la1, 1);
            la1 += __shfl_xor_sync(0xFFFFFFFFu, la1, 2);
            l0 = l0 * corr0 + la0;
            l1 = l1 * corr1 + la1;

            #pragma unroll
            for (int j = 0; j < 8; j++) {
                of[j][0] *= corr0; of[j][1] *= corr0;
                of[j][2] *= corr1; of[j][3] *= corr1;
            }

            // ---- O += P V (C-frag -> A-frag shuffles; B-frags via LDS.64) ----
            #pragma unroll
            for (int kk = 0; kk < 8; kk++) {
                uint32_t p0 = tf32u(cf[kk][0]), p1 = tf32u(cf[kk][1]);
                uint32_t p2 = tf32u(cf[kk][2]), p3 = tf32u(cf[kk][3]);
                uint32_t u0 = __shfl_sync(0xFFFFFFFFu, p0, slo);
                uint32_t u1 = __shfl_sync(0xFFFFFFFFu, p1, slo);
                uint32_t u2 = __shfl_sync(0xFFFFFFFFu, p2, slo);
                uint32_t u3 = __shfl_sync(0xFFFFFFFFu, p3, slo);
                uint32_t x0 = __shfl_sync(0xFFFFFFFFu, p0, shi);
                uint32_t x1 = __shfl_sync(0xFFFFFFFFu, p1, shi);
                uint32_t x2 = __shfl_sync(0xFFFFFFFFu, p2, shi);
                uint32_t x3 = __shfl_sync(0xFFFFFFFFu, p3, shi);
                uint32_t a0 = odd ? u1 : u0;
                uint32_t a1 = odd ? u3 : u2;
                uint32_t a2 = odd ? x1 : x0;
                uint32_t a3 = odd ? x3 : x2;
                #pragma unroll
                for (int j2 = 0; j2 < 8; j2++) {
                    const int d = j2 * 8 + (lane >> 2);
                    float2 bv = *reinterpret_cast<const float2*>(&sB[d*AP + kk*8 + cq2]);
                    mma_tf32_16x8x8(of[j2][0], of[j2][1], of[j2][2], of[j2][3],
                                    a0, a1, a2, a3,
                                    __float_as_uint(bv.x), __float_as_uint(bv.y));
                }
            }
        }
        __syncthreads();

        if (hasNext) {
            #pragma unroll
            for (int i = 0; i < 4; i++) {
                int r = kr + i * 16;
                *reinterpret_cast<float4*>(sA + r * AP + kd4 * 4) = perm_pack(pkL[i], pkH[i]);
                int d4 = vd4base + i * 4;
                sB[(d4*4+0)*AP + vpr] = tf32_rna(pv[i].x);
                sB[(d4*4+1)*AP + vpr] = tf32_rna(pv[i].y);
                sB[(d4*4+2)*AP + vpr] = tf32_rna(pv[i].z);
                sB[(d4*4+3)*AP + vpr] = tf32_rna(pv[i].w);
            }
            __syncthreads();
        }
    }

    const float inv0 = 1.f / l0, inv1 = 1.f / l1;
    #pragma unroll
    for (int j2 = 0; j2 < 8; j2++) {
        int col = j2 * 8 + 2 * cq;
        float2 v0 = make_float2(of[j2][0] * inv0, of[j2][1] * inv0);
        float2 v1 = make_float2(of[j2][2] * inv1, of[j2][3] * inv1);
        *reinterpret_cast<float2*>(&Ob[(size_t)rowg0 * D_MODEL + col]) = v0;
        *reinterpret_cast<float2*>(&Ob[(size_t)rowg1 * D_MODEL + col]) = v1;
    }
}

// ---------------------------------------------------------------------------
// Launch
// ---------------------------------------------------------------------------
extern "C" void kernel_launch(void* const* d_in, const int* in_sizes, int n_in,
                              void* d_out, int out_size)
{
    (void)in_sizes; (void)n_in; (void)out_size;
    const float* q    = (const float*)d_in[0];
    const float* k    = (const float*)d_in[1];
    const float* v    = (const float*)d_in[2];
    // d_in[3] = mask (causal tril) — analytic
    const float* wq_w = (const float*)d_in[4];
    const float* wq_b = (const float*)d_in[5];
    const float* wk_w = (const float*)d_in[6];
    const float* wk_b = (const float*)d_in[7];
    const float* wv_w = (const float*)d_in[8];
    const float* wv_b = (const float*)d_in[9];
    const float* wo_w = (const float*)d_in[10];
    const float* wo_b = (const float*)d_in[11];
    float* out = (float*)d_out;

    void *pQ, *pK, *pV, *pC;
    cudaGetSymbolAddress(&pQ, g_Q);
    cudaGetSymbolAddress(&pK, g_K);
    cudaGetSymbolAddress(&pV, g_V);
    cudaGetSymbolAddress(&pC, g_ctx);
    float* Qp = (float*)pQ;
    float* Kp = (float*)pK;
    float* Vp = (float*)pV;
    float* Cp = (float*)pC;

    cudaFuncSetAttribute(gemm_tf32_qkv,
                         cudaFuncAttributeMaxDynamicSharedMemorySize, GEMM_SMEM_BYTES);
    cudaFuncSetAttribute(gemm_tf32_mma,
                         cudaFuncAttributeMaxDynamicSharedMemorySize, GEMM_SMEM_BYTES);

    dim3 qkvGrid(D_MODEL / BN, M_TOTAL / BM, 3);   // (8, 32, 3) = 768 CTAs
    gemm_tf32_qkv<<<qkvGrid, 256, GEMM_SMEM_BYTES>>>(q, k, v, wq_w, wk_w, wv_w,
                                                     wq_b, wk_b, wv_b, Qp, Kp, Vp);

    dim3 attnGrid(SEQ / AQ, HEADS, BATCH);         // (16, 16, 2)
    flash_attn_tc<<<attnGrid, 256>>>(Qp, Kp, Vp, Cp);

    dim3 gemmGrid(D_MODEL / BN, M_TOTAL / BM);     // (8, 32)
    gemm_tf32_mma<<<gemmGrid, 256, GEMM_SMEM_BYTES>>>(Cp, wo_w, wo_b, out,
                                                      M_TOTAL, D_MODEL, D_MODEL);
}

// round 9
// speedup vs baseline: 1.2403x; 1.0429x over previous
#include <cuda_runtime.h>
#include <cstdint>
#include <cstddef>

#define D_MODEL 1024
#define HEADS   16
#define D_K     64
#define BATCH   2
#define SEQ     2048
#define M_TOTAL (BATCH * SEQ)   // 4096

// Scratch (allocation-free rule: __device__ globals)
__device__ float g_Q[M_TOTAL * D_MODEL];   // pre-scaled, tf32-rounded, d-permuted
__device__ float g_K[M_TOTAL * D_MODEL];   // tf32-rounded, d-permuted
__device__ float g_V[M_TOTAL * D_MODEL];   // tf32-rounded
__device__ float g_ctx[M_TOTAL * D_MODEL];

// ---------------------------------------------------------------------------
// tf32 helpers (baseline PTX, legal on compute_103)
// ---------------------------------------------------------------------------
__device__ __forceinline__ float tf32_rna(float x) {
    uint32_t r;
    asm("cvt.rna.tf32.f32 %0, %1;" : "=r"(r) : "f"(x));
    return __uint_as_float(r);
}
__device__ __forceinline__ uint32_t tf32u(float x) {
    uint32_t r;
    asm("cvt.rna.tf32.f32 %0, %1;" : "=r"(r) : "f"(x));
    return r;
}

__device__ __forceinline__ void mma_tf32_16x8x8(
    float& d0, float& d1, float& d2, float& d3,
    uint32_t a0, uint32_t a1, uint32_t a2, uint32_t a3,
    uint32_t b0, uint32_t b1)
{
    asm volatile(
        "mma.sync.aligned.m16n8k8.row.col.f32.tf32.tf32.f32 "
        "{%0,%1,%2,%3}, {%4,%5,%6,%7}, {%8,%9}, {%0,%1,%2,%3};"
        : "+f"(d0), "+f"(d1), "+f"(d2), "+f"(d3)
        : "r"(a0), "r"(a1), "r"(a2), "r"(a3), "r"(b0), "r"(b1));
}

// pair-permutation within each 8-group: (k, k+4) -> adjacent positions (2k', 2k'+1)
__device__ __forceinline__ int perm_idx(int k) {
    return (k & ~7) + ((k & 3) << 1) + ((k >> 2) & 1);
}

// ---------------------------------------------------------------------------
// tf32 mma.sync GEMM body (NT + bias): C[M,N] = A[M,K] * W[N,K]^T + bias[N]
// R6 configuration (proven 201us): 128x128 tile, BK=32, 8 warps, 64x32 warp
// tile, double-buffered smem, float4 staging, scalar frag LDS.
// Epilogue modes: 0 = plain fp32; 1 = tf32-rounded; 2 = tf32-rounded + column
// pair-permutation (for Q/K consumed by attention's permuted fragment loads).
// ---------------------------------------------------------------------------
#define BM  128
#define BN  128
#define BKG 32
#define PAD 4
#define LDP (BKG + PAD)                              // 36
#define TILE_FLOATS (BM * LDP)                       // 4608
#define GEMM_SMEM_BYTES (4 * TILE_FLOATS * 4)        // 73728 B

__device__ __forceinline__ void stage_store(
    float* __restrict__ As, float* __restrict__ Bs,
    const float4* pa, const float4* pb, int ldr, int ldc4)
{
    #pragma unroll
    for (int i = 0; i < 4; i++) {
        int r = ldr + i * 32;
        float4 va = pa[i], vb = pb[i];
        float4 sa, sb;
        sa.x = tf32_rna(va.x); sa.y = tf32_rna(va.y);
        sa.z = tf32_rna(va.z); sa.w = tf32_rna(va.w);
        sb.x = tf32_rna(vb.x); sb.y = tf32_rna(vb.y);
        sb.z = tf32_rna(vb.z); sb.w = tf32_rna(vb.w);
        *reinterpret_cast<float4*>(As + r * LDP + ldc4 * 4) = sa;
        *reinterpret_cast<float4*>(Bs + r * LDP + ldc4 * 4) = sb;
    }
}

__device__ __forceinline__ void gemm_body(
    const float* __restrict__ A,
    const float* __restrict__ W,
    const float* __restrict__ bias,
    float* __restrict__ C,
    int M, int N, int K, int outMode, float outScale)
{
    extern __shared__ float smp[];
    float* As0 = smp;
    float* Bs0 = smp + TILE_FLOATS;
    float* As1 = smp + 2 * TILE_FLOATS;
    float* Bs1 = smp + 3 * TILE_FLOATS;

    const int tid  = threadIdx.x;
    const int wid  = tid >> 5;
    const int lane = tid & 31;
    const int wm = wid & 1;
    const int wn = wid >> 1;
    const int rowBase = blockIdx.y * BM;
    const int colBase = blockIdx.x * BN;
    const int warpRow = wm * 64;
    const int warpCol = wn * 32;

    const int ldr  = tid >> 3;
    const int ldc4 = tid & 7;

    float acc[4][4][4];
    #pragma unroll
    for (int mt = 0; mt < 4; mt++)
        #pragma unroll
        for (int nt = 0; nt < 4; nt++)
            #pragma unroll
            for (int i = 0; i < 4; i++) acc[mt][nt][i] = 0.f;

    float4 pa[4], pb[4];

    #pragma unroll
    for (int i = 0; i < 4; i++) {
        int r = ldr + i * 32;
        pa[i] = *reinterpret_cast<const float4*>(&A[(size_t)(rowBase + r) * K + ldc4 * 4]);
        pb[i] = *reinterpret_cast<const float4*>(&W[(size_t)(colBase + r) * K + ldc4 * 4]);
    }
    stage_store(As0, Bs0, pa, pb, ldr, ldc4);
    __syncthreads();

    const int NT = K / BKG;
    for (int t = 0; t < NT; t++) {
        const float* Ac = (t & 1) ? As1 : As0;
        const float* Bc = (t & 1) ? Bs1 : Bs0;
        const bool more = (t + 1 < NT);

        if (more) {
            const int ktn = (t + 1) * BKG;
            #pragma unroll
            for (int i = 0; i < 4; i++) {
                int r = ldr + i * 32;
                pa[i] = *reinterpret_cast<const float4*>(
                    &A[(size_t)(rowBase + r) * K + ktn + ldc4 * 4]);
                pb[i] = *reinterpret_cast<const float4*>(
                    &W[(size_t)(colBase + r) * K + ktn + ldc4 * 4]);
            }
        }

        #pragma unroll
        for (int kk = 0; kk < BKG; kk += 8) {
            const int r0 = warpRow + (lane >> 2);
            const int n0 = warpCol + (lane >> 2);
            const int kA = kk + (lane & 3);
            uint32_t af[4][4], bf[4][2];
            #pragma unroll
            for (int mt = 0; mt < 4; mt++) {
                af[mt][0] = __float_as_uint(Ac[(r0 + mt*16    ) * LDP + kA    ]);
                af[mt][1] = __float_as_uint(Ac[(r0 + mt*16 + 8) * LDP + kA    ]);
                af[mt][2] = __float_as_uint(Ac[(r0 + mt*16    ) * LDP + kA + 4]);
                af[mt][3] = __float_as_uint(Ac[(r0 + mt*16 + 8) * LDP + kA + 4]);
            }
            #pragma unroll
            for (int nt = 0; nt < 4; nt++) {
                bf[nt][0] = __float_as_uint(Bc[(n0 + nt*8) * LDP + kA    ]);
                bf[nt][1] = __float_as_uint(Bc[(n0 + nt*8) * LDP + kA + 4]);
            }
            #pragma unroll
            for (int mt = 0; mt < 4; mt++)
                #pragma unroll
                for (int nt = 0; nt < 4; nt++)
                    mma_tf32_16x8x8(acc[mt][nt][0], acc[mt][nt][1],
                                    acc[mt][nt][2], acc[mt][nt][3],
                                    af[mt][0], af[mt][1], af[mt][2], af[mt][3],
                                    bf[nt][0], bf[nt][1]);
        }

        if (more) {
            float* An = (t & 1) ? As0 : As1;
            float* Bn = (t & 1) ? Bs0 : Bs1;
            stage_store(An, Bn, pa, pb, ldr, ldc4);
            __syncthreads();
        }
    }

    #pragma unroll
    for (int nt = 0; nt < 4; nt++) {
        const int col = colBase + warpCol + nt * 8 + 2 * (lane & 3);
        const float b0 = bias[col], b1 = bias[col + 1];
        #pragma unroll
        for (int mt = 0; mt < 4; mt++) {
            const int row = rowBase + warpRow + mt * 16 + (lane >> 2);
            float v0x = acc[mt][nt][0] + b0, v0y = acc[mt][nt][1] + b1;
            float v1x = acc[mt][nt][2] + b0, v1y = acc[mt][nt][3] + b1;
            if (outMode == 0) {
                *reinterpret_cast<float2*>(&C[(size_t)row * N + col]) =
                    make_float2(v0x, v0y);
                *reinterpret_cast<float2*>(&C[(size_t)(row + 8) * N + col]) =
                    make_float2(v1x, v1y);
            } else {
                v0x = tf32_rna(v0x * outScale); v0y = tf32_rna(v0y * outScale);
                v1x = tf32_rna(v1x * outScale); v1y = tf32_rna(v1y * outScale);
                if (outMode == 1) {
                    *reinterpret_cast<float2*>(&C[(size_t)row * N + col]) =
                        make_float2(v0x, v0y);
                    *reinterpret_cast<float2*>(&C[(size_t)(row + 8) * N + col]) =
                        make_float2(v1x, v1y);
                } else {
                    // mode 2: column pair-permutation; perm(c+1) = perm(c)+2
                    const int p = perm_idx(col);
                    C[(size_t)row * N + p]           = v0x;
                    C[(size_t)row * N + p + 2]       = v0y;
                    C[(size_t)(row + 8) * N + p]     = v1x;
                    C[(size_t)(row + 8) * N + p + 2] = v1y;
                }
            }
        }
    }
}

// Output projection: plain fp32 epilogue
__global__ __launch_bounds__(256, 2)
void gemm_tf32_mma(const float* __restrict__ A,
                   const float* __restrict__ W,
                   const float* __restrict__ bias,
                   float* __restrict__ C,
                   int M, int N, int K)
{
    gemm_body(A, W, bias, C, M, N, K, 0, 1.0f);
}

// Fused Q/K/V projections: blockIdx.z selects operands + epilogue mode.
// Q: round + scale(0.125) + perm; K: round + perm; V: round.
__global__ __launch_bounds__(256, 2)
void gemm_tf32_qkv(const float* __restrict__ qin,  const float* __restrict__ kin,
                   const float* __restrict__ vin,
                   const float* __restrict__ wq,   const float* __restrict__ wk,
                   const float* __restrict__ wv,
                   const float* __restrict__ bq,   const float* __restrict__ bk,
                   const float* __restrict__ bv,
                   float* __restrict__ Qo, float* __restrict__ Ko, float* __restrict__ Vo)
{
    const float *A, *W, *bias;
    float* C;
    int mode; float scale;
    if (blockIdx.z == 0)      { A = qin; W = wq; bias = bq; C = Qo; mode = 2; scale = 0.125f; }
    else if (blockIdx.z == 1) { A = kin; W = wk; bias = bk; C = Ko; mode = 2; scale = 1.0f; }
    else                      { A = vin; W = wv; bias = bv; C = Vo; mode = 1; scale = 1.0f; }
    gemm_body(A, W, bias, C, M_TOTAL, D_MODEL, D_MODEL, mode, scale);
}

// ---------------------------------------------------------------------------
// Tensor-core causal flash attention (tf32 mma.sync).
// Inputs pre-conditioned by GEMM epilogue (rounded/scaled/permuted) -> staging
// is pure copies. V stored with block-rotation layout (4-way store conflicts,
// conflict-free reads, coalesced global loads). No prefetch; 2 CTAs/SM.
// ---------------------------------------------------------------------------
#define AQ  128
#define AKV 64
#define AP  72   // 72 % 32 == 8 -> conflict-free LDS.64 frag reads

__global__ __launch_bounds__(256, 2)
void flash_attn_tc(const float* __restrict__ Qg,
                   const float* __restrict__ Kg,
                   const float* __restrict__ Vg,
                   float* __restrict__ Og)
{
    __shared__ float sA[64 * AP];   // Q rows 0-63 staging, then K tile [key][perm(d)]
    __shared__ float sB[64 * AP];   // Q rows 64-127 staging, then V tile [d][rot-perm(key)]

    const int tid  = threadIdx.x;
    const int w    = tid >> 5;
    const int lane = tid & 31;
    const int h = blockIdx.y, b = blockIdx.z;
    const int qblk = (int)gridDim.x - 1 - (int)blockIdx.x;   // heaviest-first
    const int qbase = qblk * AQ;

    const float* Qb = Qg + (size_t)b * SEQ * D_MODEL + h * D_K;
    const float* Kb = Kg + (size_t)b * SEQ * D_MODEL + h * D_K;
    const float* Vb = Vg + (size_t)b * SEQ * D_MODEL + h * D_K;
    float*       Ob = Og + (size_t)b * SEQ * D_MODEL + h * D_K;

    // ---- stage Q (already scaled/rounded/permuted): pure copy ----
    #pragma unroll
    for (int i = 0; i < 8; i++) {
        int idx = tid + i * 256;
        int r = idx >> 4, d4 = idx & 15;
        float4 v = *reinterpret_cast<const float4*>(
            &Qb[(size_t)(qbase + r) * D_MODEL + d4 * 4]);
        float* dst = (r < 64 ? sA : sB) + (r & 63) * AP + d4 * 4;
        *reinterpret_cast<float4*>(dst) = v;
    }
    __syncthreads();

    // ---- extract Q A-fragments (LDS.64 pairs on permuted layout) ----
    uint32_t qf[8][4];
    {
        const float* qsrc = (w < 4) ? sA : sB;
        int r0 = (w * 16 + (lane >> 2)) & 63;
        int c2 = (lane & 3) << 1;
        #pragma unroll
        for (int kk = 0; kk < 8; kk++) {
            float2 lo = *reinterpret_cast<const float2*>(&qsrc[ r0      * AP + kk * 8 + c2]);
            float2 hi = *reinterpret_cast<const float2*>(&qsrc[(r0 + 8) * AP + kk * 8 + c2]);
            qf[kk][0] = __float_as_uint(lo.x);
            qf[kk][2] = __float_as_uint(lo.y);
            qf[kk][1] = __float_as_uint(hi.x);
            qf[kk][3] = __float_as_uint(hi.y);
        }
    }
    __syncthreads();

    float of[8][4];
    #pragma unroll
    for (int j = 0; j < 8; j++) { of[j][0]=of[j][1]=of[j][2]=of[j][3]=0.f; }
    float m0 = -1e30f, m1 = -1e30f, l0 = 0.f, l1 = 0.f;

    const int rowg0 = qbase + w * 16 + (lane >> 2);
    const int rowg1 = rowg0 + 8;
    const int warpRowMax = qbase + w * 16 + 15;
    const int nchunks = (qbase + AQ) / AKV;

    const int cbase = lane & ~3, cq = lane & 3;
    const int cq2 = cq << 1;
    const int slo = cbase | (cq >> 1);
    const int shi = slo + 2;
    const bool odd = cq & 1;

    // staging index precompute (both K and V use the coalesced mapping)
    const int sr  = tid >> 4;       // row 0..15 (+16 per iter)
    const int sd4 = tid & 15;       // float4 index along d

    // ---- stage chunk 0 ----
    #pragma unroll
    for (int i = 0; i < 4; i++) {
        int r = sr + i * 16;
        float4 kv = *reinterpret_cast<const float4*>(&Kb[(size_t)r * D_MODEL + sd4 * 4]);
        *reinterpret_cast<float4*>(sA + r * AP + sd4 * 4) = kv;   // K already permuted
        float4 vv = *reinterpret_cast<const float4*>(&Vb[(size_t)r * D_MODEL + sd4 * 4]);
        const int colv = (perm_idx(r) + ((sd4 & 7) << 3)) & 63;   // rotation layout
        const int d = sd4 * 4;
        sB[(d + 0) * AP + colv] = vv.x;
        sB[(d + 1) * AP + colv] = vv.y;
        sB[(d + 2) * AP + colv] = vv.z;
        sB[(d + 3) * AP + colv] = vv.w;
    }
    __syncthreads();

    for (int ch = 0; ch < nchunks; ch++) {
        const int kt = ch * AKV;
        const bool hasNext = (ch + 1 < nchunks);

        if (kt <= warpRowMax) {
            // ---- S = Q K^T ----
            float cf[8][4];
            #pragma unroll
            for (int j = 0; j < 8; j++) {
                cf[j][0]=cf[j][1]=cf[j][2]=cf[j][3]=0.f;
                const int key = j * 8 + (lane >> 2);
                #pragma unroll
                for (int kk = 0; kk < 8; kk++) {
                    float2 bv = *reinterpret_cast<const float2*>(&sA[key*AP + kk*8 + cq2]);
                    mma_tf32_16x8x8(cf[j][0], cf[j][1], cf[j][2], cf[j][3],
                                    qf[kk][0], qf[kk][1], qf[kk][2], qf[kk][3],
                                    __float_as_uint(bv.x), __float_as_uint(bv.y));
                }
            }

            // ---- causal mask (diagonal-band chunks only) ----
            if (kt + AKV - 1 > qbase + w * 16) {
                #pragma unroll
                for (int j = 0; j < 8; j++) {
                    int col = kt + j * 8 + 2 * cq;
                    if (col     > rowg0) cf[j][0] = -1e30f;
                    if (col + 1 > rowg0) cf[j][1] = -1e30f;
                    if (col     > rowg1) cf[j][2] = -1e30f;
                    if (col + 1 > rowg1) cf[j][3] = -1e30f;
                }
            }

            // ---- online softmax ----
            float mx0 = -1e30f, mx1 = -1e30f;
            #pragma unroll
            for (int j = 0; j < 8; j++) {
                mx0 = fmaxf(mx0, fmaxf(cf[j][0], cf[j][1]));
                mx1 = fmaxf(mx1, fmaxf(cf[j][2], cf[j][3]));
            }
            mx0 = fmaxf(mx0, __shfl_xor_sync(0xFFFFFFFFu, mx0, 1));
            mx0 = fmaxf(mx0, __shfl_xor_sync(0xFFFFFFFFu, mx0, 2));
            mx1 = fmaxf(mx1, __shfl_xor_sync(0xFFFFFFFFu, mx1, 1));
            mx1 = fmaxf(mx1, __shfl_xor_sync(0xFFFFFFFFu, mx1, 2));

            const float mn0 = fmaxf(m0, mx0), mn1 = fmaxf(m1, mx1);
            const float corr0 = __expf(m0 - mn0), corr1 = __expf(m1 - mn1);
            m0 = mn0; m1 = mn1;

            float la0 = 0.f, la1 = 0.f;
            #pragma unroll
            for (int j = 0; j < 8; j++) {
                cf[j][0] = __expf(cf[j][0] - mn0);
                cf[j][1] = __expf(cf[j][1] - mn0);
                cf[j][2] = __expf(cf[j][2] - mn1);
                cf[j][3] = __expf(cf[j][3] - mn1);
                la0 += cf[j][0] + cf[j][1];
                la1 += cf[j][2] + cf[j][3];
            }
            la0 += __shfl_xor_sync(0xFFFFFFFFu, la0, 1);
            la0 += __shfl_xor_sync(0xFFFFFFFFu, la0, 2);
            la1 += __shfl_xor_sync(0xFFFFFFFFu, la1, 1);
            la1 += __shfl_xor_sync(0xFFFFFFFFu, la1, 2);
            l0 = l0 * corr0 + la0;
            l1 = l1 * corr1 + la1;

            #pragma unroll
            for (int j = 0; j < 8; j++) {
                of[j][0] *= corr0; of[j][1] *= corr0;
                of[j][2] *= corr1; of[j][3] *= corr1;
            }

            // ---- O += P V (C->A frag via shuffles; B-frags via rotated LDS.64) ----
            #pragma unroll
            for (int kk = 0; kk < 8; kk++) {
                uint32_t p0 = tf32u(cf[kk][0]), p1 = tf32u(cf[kk][1]);
                uint32_t p2 = tf32u(cf[kk][2]), p3 = tf32u(cf[kk][3]);
                uint32_t u0 = __shfl_sync(0xFFFFFFFFu, p0, slo);
                uint32_t u1 = __shfl_sync(0xFFFFFFFFu, p1, slo);
                uint32_t u2 = __shfl_sync(0xFFFFFFFFu, p2, slo);
                uint32_t u3 = __shfl_sync(0xFFFFFFFFu, p3, slo);
                uint32_t x0 = __shfl_sync(0xFFFFFFFFu, p0, shi);
                uint32_t x1 = __shfl_sync(0xFFFFFFFFu, p1, shi);
                uint32_t x2 = __shfl_sync(0xFFFFFFFFu, p2, shi);
                uint32_t x3 = __shfl_sync(0xFFFFFFFFu, p3, shi);
                uint32_t a0 = odd ? u1 : u0;
                uint32_t a1 = odd ? u3 : u2;
                uint32_t a2 = odd ? x1 : x0;
                uint32_t a3 = odd ? x3 : x2;
                #pragma unroll
                for (int j2 = 0; j2 < 8; j2++) {
                    const int d = j2 * 8 + (lane >> 2);
                    const int rot = ((d >> 2) & 7) << 3;
                    const int colv = (kk * 8 + cq2 + rot) & 63;
                    float2 bv = *reinterpret_cast<const float2*>(&sB[d*AP + colv]);
                    mma_tf32_16x8x8(of[j2][0], of[j2][1], of[j2][2], of[j2][3],
                                    a0, a1, a2, a3,
                                    __float_as_uint(bv.x), __float_as_uint(bv.y));
                }
            }
        }
        __syncthreads();

        if (hasNext) {
            const int ktn = kt + AKV;
            #pragma unroll
            for (int i = 0; i < 4; i++) {
                int r = sr + i * 16;
                float4 kv = *reinterpret_cast<const float4*>(
                    &Kb[(size_t)(ktn + r) * D_MODEL + sd4 * 4]);
                *reinterpret_cast<float4*>(sA + r * AP + sd4 * 4) = kv;
                float4 vv = *reinterpret_cast<const float4*>(
                    &Vb[(size_t)(ktn + r) * D_MODEL + sd4 * 4]);
                const int colv = (perm_idx(r) + ((sd4 & 7) << 3)) & 63;
                const int d = sd4 * 4;
                sB[(d + 0) * AP + colv] = vv.x;
                sB[(d + 1) * AP + colv] = vv.y;
                sB[(d + 2) * AP + colv] = vv.z;
                sB[(d + 3) * AP + colv] = vv.w;
            }
            __syncthreads();
        }
    }

    const float inv0 = 1.f / l0, inv1 = 1.f / l1;
    #pragma unroll
    for (int j2 = 0; j2 < 8; j2++) {
        int col = j2 * 8 + 2 * cq;
        float2 v0 = make_float2(of[j2][0] * inv0, of[j2][1] * inv0);
        float2 v1 = make_float2(of[j2][2] * inv1, of[j2][3] * inv1);
        *reinterpret_cast<float2*>(&Ob[(size_t)rowg0 * D_MODEL + col]) = v0;
        *reinterpret_cast<float2*>(&Ob[(size_t)rowg1 * D_MODEL + col]) = v1;
    }
}

// ---------------------------------------------------------------------------
// Launch
// ---------------------------------------------------------------------------
extern "C" void kernel_launch(void* const* d_in, const int* in_sizes, int n_in,
                              void* d_out, int out_size)
{
    (void)in_sizes; (void)n_in; (void)out_size;
    const float* q    = (const float*)d_in[0];
    const float* k    = (const float*)d_in[1];
    const float* v    = (const float*)d_in[2];
    // d_in[3] = mask (causal tril) — analytic
    const float* wq_w = (const float*)d_in[4];
    const float* wq_b = (const float*)d_in[5];
    const float* wk_w = (const float*)d_in[6];
    const float* wk_b = (const float*)d_in[7];
    const float* wv_w = (const float*)d_in[8];
    const float* wv_b = (const float*)d_in[9];
    const float* wo_w = (const float*)d_in[10];
    const float* wo_b = (const float*)d_in[11];
    float* out = (float*)d_out;

    void *pQ, *pK, *pV, *pC;
    cudaGetSymbolAddress(&pQ, g_Q);
    cudaGetSymbolAddress(&pK, g_K);
    cudaGetSymbolAddress(&pV, g_V);
    cudaGetSymbolAddress(&pC, g_ctx);
    float* Qp = (float*)pQ;
    float* Kp = (float*)pK;
    float* Vp = (float*)pV;
    float* Cp = (float*)pC;

    cudaFuncSetAttribute(gemm_tf32_qkv,
                         cudaFuncAttributeMaxDynamicSharedMemorySize, GEMM_SMEM_BYTES);
    cudaFuncSetAttribute(gemm_tf32_mma,
                         cudaFuncAttributeMaxDynamicSharedMemorySize, GEMM_SMEM_BYTES);

    dim3 qkvGrid(D_MODEL / BN, M_TOTAL / BM, 3);   // (8, 32, 3) = 768 CTAs
    gemm_tf32_qkv<<<qkvGrid, 256, GEMM_SMEM_BYTES>>>(q, k, v, wq_w, wk_w, wv_w,
                                                     wq_b, wk_b, wv_b, Qp, Kp, Vp);

    dim3 attnGrid(SEQ / AQ, HEADS, BATCH);         // (16, 16, 2)
    flash_attn_tc<<<attnGrid, 256>>>(Qp, Kp, Vp, Cp);

    dim3 gemmGrid(D_MODEL / BN, M_TOTAL / BM);     // (8, 32)
    gemm_tf32_mma<<<gemmGrid, 256, GEMM_SMEM_BYTES>>>(Cp, wo_w, wo_b, out,
                                                      M_TOTAL, D_MODEL, D_MODEL);
}

// round 10
// speedup vs baseline: 1.3363x; 1.0774x over previous
#include <cuda_runtime.h>
#include <cstdint>
#include <cstddef>

#define D_MODEL 1024
#define HEADS   16
#define D_K     64
#define BATCH   2
#define SEQ     2048
#define M_TOTAL (BATCH * SEQ)   // 4096

// Scratch (allocation-free rule: __device__ globals)
__device__ float g_Q[M_TOTAL * D_MODEL];   // pre-scaled, tf32-rounded, d-permuted
__device__ float g_K[M_TOTAL * D_MODEL];   // tf32-rounded, d-permuted
__device__ float g_V[M_TOTAL * D_MODEL];   // tf32-rounded
__device__ float g_ctx[M_TOTAL * D_MODEL];

// ---------------------------------------------------------------------------
// tf32 helpers (baseline PTX, legal on compute_103)
// ---------------------------------------------------------------------------
__device__ __forceinline__ float tf32_rna(float x) {
    uint32_t r;
    asm("cvt.rna.tf32.f32 %0, %1;" : "=r"(r) : "f"(x));
    return __uint_as_float(r);
}
__device__ __forceinline__ uint32_t tf32u(float x) {
    uint32_t r;
    asm("cvt.rna.tf32.f32 %0, %1;" : "=r"(r) : "f"(x));
    return r;
}

__device__ __forceinline__ void mma_tf32_16x8x8(
    float& d0, float& d1, float& d2, float& d3,
    uint32_t a0, uint32_t a1, uint32_t a2, uint32_t a3,
    uint32_t b0, uint32_t b1)
{
    asm volatile(
        "mma.sync.aligned.m16n8k8.row.col.f32.tf32.tf32.f32 "
        "{%0,%1,%2,%3}, {%4,%5,%6,%7}, {%8,%9}, {%0,%1,%2,%3};"
        : "+f"(d0), "+f"(d1), "+f"(d2), "+f"(d3)
        : "r"(a0), "r"(a1), "r"(a2), "r"(a3), "r"(b0), "r"(b1));
}

// pair-permutation within each 8-group: (k, k+4) -> adjacent positions
__device__ __forceinline__ int perm_idx(int k) {
    return (k & ~7) + ((k & 3) << 1) + ((k >> 2) & 1);
}

// ---------------------------------------------------------------------------
// tf32 mma.sync GEMM (NT + bias): C[M,N] = A[M,K] * W[N,K]^T + bias[N]
// CTA tile 128x256, BK=32, 256 threads (8 warps, 2x4), WARP TILE 64x64
// (crossbar bytes/FLOP = 0.0625 vs 0.094 at 64x32). Double-buffered smem.
// Epilogue modes: 0 plain fp32; 1 tf32-round(+scale); 2 mode1 + col perm.
// ---------------------------------------------------------------------------
#define BM  128
#define BN  256
#define BKG 32
#define PAD 4
#define LDP (BKG + PAD)                              // 36
#define A_TILE (BM * LDP)                            // 4608 floats
#define B_TILE (BN * LDP)                            // 9216 floats
#define STAGE_FLOATS (A_TILE + B_TILE)               // 13824
#define GEMM_SMEM_BYTES (2 * STAGE_FLOATS * 4)       // 110592 B

__device__ __forceinline__ void gemm_body(
    const float* __restrict__ A,
    const float* __restrict__ W,
    const float* __restrict__ bias,
    float* __restrict__ C,
    int M, int N, int K, int outMode, float outScale)
{
    extern __shared__ float smp[];
    float* As0 = smp;
    float* Bs0 = smp + A_TILE;
    float* As1 = smp + STAGE_FLOATS;
    float* Bs1 = smp + STAGE_FLOATS + A_TILE;

    const int tid  = threadIdx.x;
    const int wid  = tid >> 5;
    const int lane = tid & 31;
    const int wm = wid & 1;       // 0..1
    const int wn = wid >> 1;      // 0..3
    const int rowBase = blockIdx.y * BM;
    const int colBase = blockIdx.x * BN;
    const int warpRow = wm * 64;
    const int warpCol = wn * 64;

    const int ldr  = tid >> 3;    // 0..31 (+32 steps)
    const int ldc4 = tid & 7;     // float4 along k

    float acc[4][8][4];
    #pragma unroll
    for (int mt = 0; mt < 4; mt++)
        #pragma unroll
        for (int nt = 0; nt < 8; nt++)
            #pragma unroll
            for (int i = 0; i < 4; i++) acc[mt][nt][i] = 0.f;

    float4 pa[4], pb[8];

    // prologue: tile 0
    #pragma unroll
    for (int i = 0; i < 4; i++) {
        int r = ldr + i * 32;
        pa[i] = *reinterpret_cast<const float4*>(&A[(size_t)(rowBase + r) * K + ldc4 * 4]);
    }
    #pragma unroll
    for (int i = 0; i < 8; i++) {
        int r = ldr + i * 32;
        pb[i] = *reinterpret_cast<const float4*>(&W[(size_t)(colBase + r) * K + ldc4 * 4]);
    }
    #pragma unroll
    for (int i = 0; i < 4; i++) {
        int r = ldr + i * 32;
        float4 v = pa[i], s;
        s.x = tf32_rna(v.x); s.y = tf32_rna(v.y); s.z = tf32_rna(v.z); s.w = tf32_rna(v.w);
        *reinterpret_cast<float4*>(As0 + r * LDP + ldc4 * 4) = s;
    }
    #pragma unroll
    for (int i = 0; i < 8; i++) {
        int r = ldr + i * 32;
        float4 v = pb[i], s;
        s.x = tf32_rna(v.x); s.y = tf32_rna(v.y); s.z = tf32_rna(v.z); s.w = tf32_rna(v.w);
        *reinterpret_cast<float4*>(Bs0 + r * LDP + ldc4 * 4) = s;
    }
    __syncthreads();

    const int NT = K / BKG;
    for (int t = 0; t < NT; t++) {
        const float* Ac = (t & 1) ? As1 : As0;
        const float* Bc = (t & 1) ? Bs1 : Bs0;
        const bool more = (t + 1 < NT);

        if (more) {
            const int ktn = (t + 1) * BKG;
            #pragma unroll
            for (int i = 0; i < 4; i++) {
                int r = ldr + i * 32;
                pa[i] = *reinterpret_cast<const float4*>(
                    &A[(size_t)(rowBase + r) * K + ktn + ldc4 * 4]);
            }
            #pragma unroll
            for (int i = 0; i < 8; i++) {
                int r = ldr + i * 32;
                pb[i] = *reinterpret_cast<const float4*>(
                    &W[(size_t)(colBase + r) * K + ktn + ldc4 * 4]);
            }
        }

        const int r0 = warpRow + (lane >> 2);
        const int n0 = warpCol + (lane >> 2);
        #pragma unroll
        for (int kk = 0; kk < BKG; kk += 8) {
            const int kA = kk + (lane & 3);
            uint32_t af[4][4], bf[8][2];
            #pragma unroll
            for (int mt = 0; mt < 4; mt++) {
                af[mt][0] = __float_as_uint(Ac[(r0 + mt*16    ) * LDP + kA    ]);
                af[mt][1] = __float_as_uint(Ac[(r0 + mt*16 + 8) * LDP + kA    ]);
                af[mt][2] = __float_as_uint(Ac[(r0 + mt*16    ) * LDP + kA + 4]);
                af[mt][3] = __float_as_uint(Ac[(r0 + mt*16 + 8) * LDP + kA + 4]);
            }
            #pragma unroll
            for (int nt = 0; nt < 8; nt++) {
                bf[nt][0] = __float_as_uint(Bc[(n0 + nt*8) * LDP + kA    ]);
                bf[nt][1] = __float_as_uint(Bc[(n0 + nt*8) * LDP + kA + 4]);
            }
            #pragma unroll
            for (int mt = 0; mt < 4; mt++)
                #pragma unroll
                for (int nt = 0; nt < 8; nt++)
                    mma_tf32_16x8x8(acc[mt][nt][0], acc[mt][nt][1],
                                    acc[mt][nt][2], acc[mt][nt][3],
                                    af[mt][0], af[mt][1], af[mt][2], af[mt][3],
                                    bf[nt][0], bf[nt][1]);
        }

        if (more) {
            float* An = (t & 1) ? As0 : As1;
            float* Bn = (t & 1) ? Bs0 : Bs1;
            #pragma unroll
            for (int i = 0; i < 4; i++) {
                int r = ldr + i * 32;
                float4 v = pa[i], s;
                s.x = tf32_rna(v.x); s.y = tf32_rna(v.y);
                s.z = tf32_rna(v.z); s.w = tf32_rna(v.w);
                *reinterpret_cast<float4*>(An + r * LDP + ldc4 * 4) = s;
            }
            #pragma unroll
            for (int i = 0; i < 8; i++) {
                int r = ldr + i * 32;
                float4 v = pb[i], s;
                s.x = tf32_rna(v.x); s.y = tf32_rna(v.y);
                s.z = tf32_rna(v.z); s.w = tf32_rna(v.w);
                *reinterpret_cast<float4*>(Bn + r * LDP + ldc4 * 4) = s;
            }
            __syncthreads();
        }
    }

    // epilogue
    #pragma unroll
    for (int nt = 0; nt < 8; nt++) {
        const int col = colBase + warpCol + nt * 8 + 2 * (lane & 3);
        const float b0 = bias[col], b1 = bias[col + 1];
        #pragma unroll
        for (int mt = 0; mt < 4; mt++) {
            const int row = rowBase + warpRow + mt * 16 + (lane >> 2);
            float v0x = acc[mt][nt][0] + b0, v0y = acc[mt][nt][1] + b1;
            float v1x = acc[mt][nt][2] + b0, v1y = acc[mt][nt][3] + b1;
            if (outMode == 0) {
                *reinterpret_cast<float2*>(&C[(size_t)row * N + col]) =
                    make_float2(v0x, v0y);
                *reinterpret_cast<float2*>(&C[(size_t)(row + 8) * N + col]) =
                    make_float2(v1x, v1y);
            } else {
                v0x = tf32_rna(v0x * outScale); v0y = tf32_rna(v0y * outScale);
                v1x = tf32_rna(v1x * outScale); v1y = tf32_rna(v1y * outScale);
                if (outMode == 1) {
                    *reinterpret_cast<float2*>(&C[(size_t)row * N + col]) =
                        make_float2(v0x, v0y);
                    *reinterpret_cast<float2*>(&C[(size_t)(row + 8) * N + col]) =
                        make_float2(v1x, v1y);
                } else {
                    const int p = perm_idx(col);
                    C[(size_t)row * N + p]           = v0x;
                    C[(size_t)row * N + p + 2]       = v0y;
                    C[(size_t)(row + 8) * N + p]     = v1x;
                    C[(size_t)(row + 8) * N + p + 2] = v1y;
                }
            }
        }
    }
}

// Output projection: plain fp32 epilogue
__global__ __launch_bounds__(256, 1)
void gemm_tf32_mma(const float* __restrict__ A,
                   const float* __restrict__ W,
                   const float* __restrict__ bias,
                   float* __restrict__ C,
                   int M, int N, int K)
{
    gemm_body(A, W, bias, C, M, N, K, 0, 1.0f);
}

// Fused Q/K/V projections: blockIdx.z selects operands + epilogue mode.
__global__ __launch_bounds__(256, 1)
void gemm_tf32_qkv(const float* __restrict__ qin,  const float* __restrict__ kin,
                   const float* __restrict__ vin,
                   const float* __restrict__ wq,   const float* __restrict__ wk,
                   const float* __restrict__ wv,
                   const float* __restrict__ bq,   const float* __restrict__ bk,
                   const float* __restrict__ bv,
                   float* __restrict__ Qo, float* __restrict__ Ko, float* __restrict__ Vo)
{
    const float *A, *W, *bias;
    float* C;
    int mode; float scale;
    if (blockIdx.z == 0)      { A = qin; W = wq; bias = bq; C = Qo; mode = 2; scale = 0.125f; }
    else if (blockIdx.z == 1) { A = kin; W = wk; bias = bk; C = Ko; mode = 2; scale = 1.0f; }
    else                      { A = vin; W = wv; bias = bv; C = Vo; mode = 1; scale = 1.0f; }
    gemm_body(A, W, bias, C, M_TOTAL, D_MODEL, D_MODEL, mode, scale);
}

// ---------------------------------------------------------------------------
// Tensor-core causal flash attention (tf32 mma.sync) — unchanged from R9.
// Inputs pre-conditioned by GEMM epilogue; V block-rotation layout; 2 CTAs/SM.
// ---------------------------------------------------------------------------
#define AQ  128
#define AKV 64
#define AP  72

__global__ __launch_bounds__(256, 2)
void flash_attn_tc(const float* __restrict__ Qg,
                   const float* __restrict__ Kg,
                   const float* __restrict__ Vg,
                   float* __restrict__ Og)
{
    __shared__ float sA[64 * AP];
    __shared__ float sB[64 * AP];

    const int tid  = threadIdx.x;
    const int w    = tid >> 5;
    const int lane = tid & 31;
    const int h = blockIdx.y, b = blockIdx.z;
    const int qblk = (int)gridDim.x - 1 - (int)blockIdx.x;
    const int qbase = qblk * AQ;

    const float* Qb = Qg + (size_t)b * SEQ * D_MODEL + h * D_K;
    const float* Kb = Kg + (size_t)b * SEQ * D_MODEL + h * D_K;
    const float* Vb = Vg + (size_t)b * SEQ * D_MODEL + h * D_K;
    float*       Ob = Og + (size_t)b * SEQ * D_MODEL + h * D_K;

    #pragma unroll
    for (int i = 0; i < 8; i++) {
        int idx = tid + i * 256;
        int r = idx >> 4, d4 = idx & 15;
        float4 v = *reinterpret_cast<const float4*>(
            &Qb[(size_t)(qbase + r) * D_MODEL + d4 * 4]);
        float* dst = (r < 64 ? sA : sB) + (r & 63) * AP + d4 * 4;
        *reinterpret_cast<float4*>(dst) = v;
    }
    __syncthreads();

    uint32_t qf[8][4];
    {
        const float* qsrc = (w < 4) ? sA : sB;
        int r0 = (w * 16 + (lane >> 2)) & 63;
        int c2 = (lane & 3) << 1;
        #pragma unroll
        for (int kk = 0; kk < 8; kk++) {
            float2 lo = *reinterpret_cast<const float2*>(&qsrc[ r0      * AP + kk * 8 + c2]);
            float2 hi = *reinterpret_cast<const float2*>(&qsrc[(r0 + 8) * AP + kk * 8 + c2]);
            qf[kk][0] = __float_as_uint(lo.x);
            qf[kk][2] = __float_as_uint(lo.y);
            qf[kk][1] = __float_as_uint(hi.x);
            qf[kk][3] = __float_as_uint(hi.y);
        }
    }
    __syncthreads();

    float of[8][4];
    #pragma unroll
    for (int j = 0; j < 8; j++) { of[j][0]=of[j][1]=of[j][2]=of[j][3]=0.f; }
    float m0 = -1e30f, m1 = -1e30f, l0 = 0.f, l1 = 0.f;

    const int rowg0 = qbase + w * 16 + (lane >> 2);
    const int rowg1 = rowg0 + 8;
    const int warpRowMax = qbase + w * 16 + 15;
    const int nchunks = (qbase + AQ) / AKV;

    const int cbase = lane & ~3, cq = lane & 3;
    const int cq2 = cq << 1;
    const int slo = cbase | (cq >> 1);
    const int shi = slo + 2;
    const bool odd = cq & 1;

    const int sr  = tid >> 4;
    const int sd4 = tid & 15;

    #pragma unroll
    for (int i = 0; i < 4; i++) {
        int r = sr + i * 16;
        float4 kv = *reinterpret_cast<const float4*>(&Kb[(size_t)r * D_MODEL + sd4 * 4]);
        *reinterpret_cast<float4*>(sA + r * AP + sd4 * 4) = kv;
        float4 vv = *reinterpret_cast<const float4*>(&Vb[(size_t)r * D_MODEL + sd4 * 4]);
        const int colv = (perm_idx(r) + ((sd4 & 7) << 3)) & 63;
        const int d = sd4 * 4;
        sB[(d + 0) * AP + colv] = vv.x;
        sB[(d + 1) * AP + colv] = vv.y;
        sB[(d + 2) * AP + colv] = vv.z;
        sB[(d + 3) * AP + colv] = vv.w;
    }
    __syncthreads();

    for (int ch = 0; ch < nchunks; ch++) {
        const int kt = ch * AKV;
        const bool hasNext = (ch + 1 < nchunks);

        if (kt <= warpRowMax) {
            float cf[8][4];
            #pragma unroll
            for (int j = 0; j < 8; j++) {
                cf[j][0]=cf[j][1]=cf[j][2]=cf[j][3]=0.f;
                const int key = j * 8 + (lane >> 2);
                #pragma unroll
                for (int kk = 0; kk < 8; kk++) {
                    float2 bv = *reinterpret_cast<const float2*>(&sA[key*AP + kk*8 + cq2]);
                    mma_tf32_16x8x8(cf[j][0], cf[j][1], cf[j][2], cf[j][3],
                                    qf[kk][0], qf[kk][1], qf[kk][2], qf[kk][3],
                                    __float_as_uint(bv.x), __float_as_uint(bv.y));
                }
            }

            if (kt + AKV - 1 > qbase + w * 16) {
                #pragma unroll
                for (int j = 0; j < 8; j++) {
                    int col = kt + j * 8 + 2 * cq;
                    if (col     > rowg0) cf[j][0] = -1e30f;
                    if (col + 1 > rowg0) cf[j][1] = -1e30f;
                    if (col     > rowg1) cf[j][2] = -1e30f;
                    if (col + 1 > rowg1) cf[j][3] = -1e30f;
                }
            }

            float mx0 = -1e30f, mx1 = -1e30f;
            #pragma unroll
            for (int j = 0; j < 8; j++) {
                mx0 = fmaxf(mx0, fmaxf(cf[j][0], cf[j][1]));
                mx1 = fmaxf(mx1, fmaxf(cf[j][2], cf[j][3]));
            }
            mx0 = fmaxf(mx0, __shfl_xor_sync(0xFFFFFFFFu, mx0, 1));
            mx0 = fmaxf(mx0, __shfl_xor_sync(0xFFFFFFFFu, mx0, 2));
            mx1 = fmaxf(mx1, __shfl_xor_sync(0xFFFFFFFFu, mx1, 1));
            mx1 = fmaxf(mx1, __shfl_xor_sync(0xFFFFFFFFu, mx1, 2));

            const float mn0 = fmaxf(m0, mx0), mn1 = fmaxf(m1, mx1);
            const float corr0 = __expf(m0 - mn0), corr1 = __expf(m1 - mn1);
            m0 = mn0; m1 = mn1;

            float la0 = 0.f, la1 = 0.f;
            #pragma unroll
            for (int j = 0; j < 8; j++) {
                cf[j][0] = __expf(cf[j][0] - mn0);
                cf[j][1] = __expf(cf[j][1] - mn0);
                cf[j][2] = __expf(cf[j][2] - mn1);
                cf[j][3] = __expf(cf[j][3] - mn1);
                la0 += cf[j][0] + cf[j][1];
                la1 += cf[j][2] + cf[j][3];
            }
            la0 += __shfl_xor_sync(0xFFFFFFFFu, la0, 1);
            la0 += __shfl_xor_sync(0xFFFFFFFFu, la0, 2);
            la1 += __shfl_xor_sync(0xFFFFFFFFu, la1, 1);
            la1 += __shfl_xor_sync(0xFFFFFFFFu, la1, 2);
            l0 = l0 * corr0 + la0;
            l1 = l1 * corr1 + la1;

            #pragma unroll
            for (int j = 0; j < 8; j++) {
                of[j][0] *= corr0; of[j][1] *= corr0;
                of[j][2] *= corr1; of[j][3] *= corr1;
            }

            #pragma unroll
            for (int kk = 0; kk < 8; kk++) {
                uint32_t p0 = tf32u(cf[kk][0]), p1 = tf32u(cf[kk][1]);
                uint32_t p2 = tf32u(cf[kk][2]), p3 = tf32u(cf[kk][3]);
                uint32_t u0 = __shfl_sync(0xFFFFFFFFu, p0, slo);
                uint32_t u1 = __shfl_sync(0xFFFFFFFFu, p1, slo);
                uint32_t u2 = __shfl_sync(0xFFFFFFFFu, p2, slo);
                uint32_t u3 = __shfl_sync(0xFFFFFFFFu, p3, slo);
                uint32_t x0 = __shfl_sync(0xFFFFFFFFu, p0, shi);
                uint32_t x1 = __shfl_sync(0xFFFFFFFFu, p1, shi);
                uint32_t x2 = __shfl_sync(0xFFFFFFFFu, p2, shi);
                uint32_t x3 = __shfl_sync(0xFFFFFFFFu, p3, shi);
                uint32_t a0 = odd ? u1 : u0;
                uint32_t a1 = odd ? u3 : u2;
                uint32_t a2 = odd ? x1 : x0;
                uint32_t a3 = odd ? x3 : x2;
                #pragma unroll
                for (int j2 = 0; j2 < 8; j2++) {
                    const int d = j2 * 8 + (lane >> 2);
                    const int rot = ((d >> 2) & 7) << 3;
                    const int colv = (kk * 8 + cq2 + rot) & 63;
                    float2 bv = *reinterpret_cast<const float2*>(&sB[d*AP + colv]);
                    mma_tf32_16x8x8(of[j2][0], of[j2][1], of[j2][2], of[j2][3],
                                    a0, a1, a2, a3,
                                    __float_as_uint(bv.x), __float_as_uint(bv.y));
                }
            }
        }
        __syncthreads();

        if (hasNext) {
            const int ktn = kt + AKV;
            #pragma unroll
            for (int i = 0; i < 4; i++) {
                int r = sr + i * 16;
                float4 kv = *reinterpret_cast<const float4*>(
                    &Kb[(size_t)(ktn + r) * D_MODEL + sd4 * 4]);
                *reinterpret_cast<float4*>(sA + r * AP + sd4 * 4) = kv;
                float4 vv = *reinterpret_cast<const float4*>(
                    &Vb[(size_t)(ktn + r) * D_MODEL + sd4 * 4]);
                const int colv = (perm_idx(r) + ((sd4 & 7) << 3)) & 63;
                const int d = sd4 * 4;
                sB[(d + 0) * AP + colv] = vv.x;
                sB[(d + 1) * AP + colv] = vv.y;
                sB[(d + 2) * AP + colv] = vv.z;
                sB[(d + 3) * AP + colv] = vv.w;
            }
            __syncthreads();
        }
    }

    const float inv0 = 1.f / l0, inv1 = 1.f / l1;
    #pragma unroll
    for (int j2 = 0; j2 < 8; j2++) {
        int col = j2 * 8 + 2 * cq;
        float2 v0 = make_float2(of[j2][0] * inv0, of[j2][1] * inv0);
        float2 v1 = make_float2(of[j2][2] * inv1, of[j2][3] * inv1);
        *reinterpret_cast<float2*>(&Ob[(size_t)rowg0 * D_MODEL + col]) = v0;
        *reinterpret_cast<float2*>(&Ob[(size_t)rowg1 * D_MODEL + col]) = v1;
    }
}

// ---------------------------------------------------------------------------
// Launch
// ---------------------------------------------------------------------------
extern "C" void kernel_launch(void* const* d_in, const int* in_sizes, int n_in,
                              void* d_out, int out_size)
{
    (void)in_sizes; (void)n_in; (void)out_size;
    const float* q    = (const float*)d_in[0];
    const float* k    = (const float*)d_in[1];
    const float* v    = (const float*)d_in[2];
    // d_in[3] = mask (causal tril) — analytic
    const float* wq_w = (const float*)d_in[4];
    const float* wq_b = (const float*)d_in[5];
    const float* wk_w = (const float*)d_in[6];
    const float* wk_b = (const float*)d_in[7];
    const float* wv_w = (const float*)d_in[8];
    const float* wv_b = (const float*)d_in[9];
    const float* wo_w = (const float*)d_in[10];
    const float* wo_b = (const float*)d_in[11];
    float* out = (float*)d_out;

    void *pQ, *pK, *pV, *pC;
    cudaGetSymbolAddress(&pQ, g_Q);
    cudaGetSymbolAddress(&pK, g_K);
    cudaGetSymbolAddress(&pV, g_V);
    cudaGetSymbolAddress(&pC, g_ctx);
    float* Qp = (float*)pQ;
    float* Kp = (float*)pK;
    float* Vp = (float*)pV;
    float* Cp = (float*)pC;

    cudaFuncSetAttribute(gemm_tf32_qkv,
                         cudaFuncAttributeMaxDynamicSharedMemorySize, GEMM_SMEM_BYTES);
    cudaFuncSetAttribute(gemm_tf32_mma,
                         cudaFuncAttributeMaxDynamicSharedMemorySize, GEMM_SMEM_BYTES);

    dim3 qkvGrid(D_MODEL / BN, M_TOTAL / BM, 3);   // (4, 32, 3) = 384 CTAs
    gemm_tf32_qkv<<<qkvGrid, 256, GEMM_SMEM_BYTES>>>(q, k, v, wq_w, wk_w, wv_w,
                                                     wq_b, wk_b, wv_b, Qp, Kp, Vp);

    dim3 attnGrid(SEQ / AQ, HEADS, BATCH);         // (16, 16, 2)
    flash_attn_tc<<<attnGrid, 256>>>(Qp, Kp, Vp, Cp);

    dim3 gemmGrid(D_MODEL / BN, M_TOTAL / BM);     // (4, 32)
    gemm_tf32_mma<<<gemmGrid, 256, GEMM_SMEM_BYTES>>>(Cp, wo_w, wo_b, out,
                                                      M_TOTAL, D_MODEL, D_MODEL);
}